// round 13
// baseline (speedup 1.0000x reference)
#include <cuda_runtime.h>
#include <cuda_bf16.h>
#include <cstdint>

#define B_TOTAL 262144
#define IN_DIM 28
#define HID 128
#define LAT 64
#define NCODES 512
#define GRID1 148
#define ITER_M 256
#define NITER (B_TOTAL / ITER_M)    // 1024

#define ETHREADS 512
#define EWARPS 16

// ---- k_encode smem layout (bytes) ----
#define OF_HT    0                      // 65536: h tiles (128-row sub); CB staging at init
#define OF_ZBH   65536                  // z hi 256x128B = 32768
#define OF_ZBL   98304                  // z lo 32768
#define OF_W2    131072                 // W2H0,W2H1,W2L0,W2L1 (8K each) = 32768
#define OF_W1TH  163840                 // W1^T hi [128n][32k] 64B rows = 8192
#define OF_W1TL  172032                 // 8192
#define OF_B1    180224                 // 512
#define OF_B2    180736                 // 256
#define OF_E2    180992                 // 2048
#define OF_CD    183040                 // float[256][17] = 17408
#define OF_CI    200448                 // u16[256][17]   = 8704
#define SMEM_E   209152

// XOR swizzle, 128B rows (16B granularity)
#define SWZ_W(row, w)  ((row) * 128 + ((((w) >> 2) ^ ((row) & 7)) << 4) + ((w) & 3) * 4)
#define SWZ_C(row, ch) ((row) * 128 + ((((ch)) ^ ((row) & 7)) << 4))
// XOR swizzle, 64B rows
#define SWZ64_W(row, w)  ((row) * 64 + ((((w) >> 2) ^ (((row) >> 1) & 3)) << 4) + ((w) & 3) * 4)
#define SWZ64_C(row, ch) ((row) * 64 + ((((ch)) ^ (((row) >> 1) & 3)) << 4))

#define KOUT_GRID 592

__device__ int    g_idx[B_TOTAL];
__device__ float  g_vq_part[GRID1];
__device__ float  g_rec_part[KOUT_GRID];
__device__ float  g_hd[NCODES * HID];
__device__ float  g_tbl[NCODES * IN_DIM];

// ---------------- helpers ----------------
__device__ __forceinline__ uint32_t smem_u32_of(const void* p) {
    uint32_t a;
    asm("{ .reg .u64 t; cvta.to.shared.u64 t, %1; cvt.u32.u64 %0, t; }" : "=r"(a) : "l"(p));
    return a;
}
__device__ __forceinline__ void ldsm_x4(uint32_t* r, uint32_t addr) {
    asm volatile("ldmatrix.sync.aligned.m8n8.x4.shared.b16 {%0,%1,%2,%3}, [%4];"
        : "=r"(r[0]), "=r"(r[1]), "=r"(r[2]), "=r"(r[3]) : "r"(addr));
}
__device__ __forceinline__ void mma16816(float* d, const uint32_t* a, uint32_t b0, uint32_t b1) {
    asm volatile("mma.sync.aligned.m16n8k16.row.col.f32.bf16.bf16.f32 "
        "{%0,%1,%2,%3}, {%4,%5,%6,%7}, {%8,%9}, {%0,%1,%2,%3};"
        : "+f"(d[0]), "+f"(d[1]), "+f"(d[2]), "+f"(d[3])
        : "r"(a[0]), "r"(a[1]), "r"(a[2]), "r"(a[3]), "r"(b0), "r"(b1));
}
__device__ __forceinline__ void bf16_split(float v, __nv_bfloat16& hi, __nv_bfloat16& lo) {
    hi = __float2bfloat16(v);
    lo = __float2bfloat16(v - __bfloat162float(hi));
}
__device__ __forceinline__ uint32_t pack2_split_hi(float a, float b, uint32_t& lo_out) {
    __nv_bfloat16 ha, la, hb, lb;
    bf16_split(a, ha, la); bf16_split(b, hb, lb);
    __nv_bfloat162 ph; ph.x = ha; ph.y = hb;
    __nv_bfloat162 pl; pl.x = la; pl.y = lb;
    lo_out = *(uint32_t*)&pl;
    return *(uint32_t*)&ph;
}

// ============================================================================
// K1: encoder — 256-row iterations; x A-fragments loaded direct from global;
//     sub-tiled MMA enc1/enc2 with pair barriers; register-fed distance MMA
// ============================================================================
__global__ void __launch_bounds__(ETHREADS, 1)
k_encode(const float* __restrict__ x,
         const float* __restrict__ w1, const float* __restrict__ b1,
         const float* __restrict__ w2, const float* __restrict__ b2,
         const float* __restrict__ cb)
{
    extern __shared__ char smem[];
    const uint32_t smb = smem_u32_of(smem);

    float* s_b1 = (float*)(smem + OF_B1);
    float* s_b2 = (float*)(smem + OF_B2);
    float* s_e2 = (float*)(smem + OF_E2);
    float* s_cd = (float*)(smem + OF_CD);
    unsigned short* s_ci = (unsigned short*)(smem + OF_CI);

    const int tid = threadIdx.x;
    const int warp = tid >> 5, lane = tid & 31;

    // ---- init: weights, biases, e2; CBH staged into HT ----
    for (int i = tid; i < HID; i += ETHREADS) s_b1[i] = b1[i];
    for (int i = tid; i < LAT; i += ETHREADS) s_b2[i] = b2[i];
    for (int i = tid; i < NCODES * 32; i += ETHREADS) {      // CBH staging
        int c = i >> 5, w = i & 31;
        uint32_t lo;
        uint32_t hi = pack2_split_hi(cb[c * LAT + 2 * w], cb[c * LAT + 2 * w + 1], lo);
        *(uint32_t*)(smem + OF_HT + SWZ_W(c, w)) = hi;
        (void)lo;
    }
    for (int i = tid; i < LAT * 64; i += ETHREADS) {         // W2^T split
        int n = i >> 6, kw = i & 63;
        uint32_t lo;
        uint32_t hi = pack2_split_hi(w2[2 * kw * LAT + n], w2[(2 * kw + 1) * LAT + n], lo);
        int khalf = kw >> 5, w = kw & 31;
        *(uint32_t*)(smem + OF_W2 + khalf * 8192 + SWZ_W(n, w))         = hi;
        *(uint32_t*)(smem + OF_W2 + 16384 + khalf * 8192 + SWZ_W(n, w)) = lo;
    }
    for (int i = tid; i < HID * 14; i += ETHREADS) {         // W1^T split
        int n = i / 14, kw = i - n * 14;
        uint32_t lo;
        uint32_t hi = pack2_split_hi(w1[2 * kw * HID + n], w1[(2 * kw + 1) * HID + n], lo);
        *(uint32_t*)(smem + OF_W1TH + SWZ64_W(n, kw)) = hi;
        *(uint32_t*)(smem + OF_W1TL + SWZ64_W(n, kw)) = lo;
    }
    for (int i = tid; i < HID * 2; i += ETHREADS) {          // W1T k-pad
        int n = i >> 1, w = 14 + (i & 1);
        *(uint32_t*)(smem + OF_W1TH + SWZ64_W(n, w)) = 0;
        *(uint32_t*)(smem + OF_W1TL + SWZ64_W(n, w)) = 0;
    }
    for (int c = tid; c < NCODES; c += ETHREADS) {
        float s = 0.f;
        for (int k = 0; k < LAT; k++) { float v = cb[c * LAT + k]; s = fmaf(v, v, s); }
        s_e2[c] = s;
    }
    __syncthreads();

    // mma lane-role constants
    const int g = lane >> 2, t = lane & 3;
    const int a_roff = (lane & 7) + 8 * ((lane >> 3) & 1);
    const int a_ch   = lane >> 4;
    const int b_row0 = (lane & 7) + 8 * ((lane >> 4) & 1);
    const int b_ch   = (lane >> 3) & 1;

    // ---- codebook HI fragments -> registers ----
    uint32_t bregH[4][4][2];
    #pragma unroll
    for (int pp = 0; pp < 2; pp++)
        #pragma unroll
        for (int kk = 0; kk < 4; kk++) {
            uint32_t r4[4];
            ldsm_x4(r4, smb + OF_HT + SWZ_C(warp * 32 + pp * 16 + b_row0, 2 * kk + b_ch));
            bregH[2 * pp][kk][0] = r4[0];     bregH[2 * pp][kk][1] = r4[1];
            bregH[2 * pp + 1][kk][0] = r4[2]; bregH[2 * pp + 1][kk][1] = r4[3];
        }
    __syncthreads();
    // ---- restage CBL into HT, then codebook LO fragments -> registers ----
    for (int i = tid; i < NCODES * 32; i += ETHREADS) {
        int c = i >> 5, w = i & 31;
        uint32_t lo;
        (void)pack2_split_hi(cb[c * LAT + 2 * w], cb[c * LAT + 2 * w + 1], lo);
        *(uint32_t*)(smem + OF_HT + SWZ_W(c, w)) = lo;
    }
    __syncthreads();
    uint32_t bregL[4][4][2];
    #pragma unroll
    for (int pp = 0; pp < 2; pp++)
        #pragma unroll
        for (int kk = 0; kk < 4; kk++) {
            uint32_t r4[4];
            ldsm_x4(r4, smb + OF_HT + SWZ_C(warp * 32 + pp * 16 + b_row0, 2 * kk + b_ch));
            bregL[2 * pp][kk][0] = r4[0];     bregL[2 * pp][kk][1] = r4[1];
            bregL[2 * pp + 1][kk][0] = r4[2]; bregL[2 * pp + 1][kk][1] = r4[3];
        }
    __syncthreads();   // HT now free for h tiles

    const int rbw = warp >> 1, nhf = warp & 1;
    const int R0w = rbw * 16;
    const int rA = R0w + g, rB = rA + 8;     // HT-local rows
    float vq_local = 0.f;

    for (int tle = blockIdx.x; tle < NITER; tle += GRID1) {
        // -------- P1/P2 over two 128-row sub-tiles through the shared HT --------
        #pragma unroll
        for (int sub = 0; sub < 2; sub++) {
            const int zoff = sub * 128;

            // ---- P1: enc1 MMA: x A-frags direct from global; h -> HT tiles ----
            {
                // build A-fragments from global x (zero-pad k>=28)
                uint32_t xH[2][4], xL[2][4];
                {
                    const float* xa = x + ((size_t)tle * ITER_M + zoff + R0w + g) * IN_DIM;
                    const float* xb = xa + 8 * IN_DIM;
                    #pragma unroll
                    for (int kk = 0; kk < 2; kk++)
                        #pragma unroll
                        for (int seg = 0; seg < 2; seg++) {
                            int k = kk * 16 + seg * 8 + 2 * t;
                            float a0 = 0.f, a1 = 0.f, c0 = 0.f, c1 = 0.f;
                            if (k < IN_DIM) {
                                float2 va = *(const float2*)(xa + k);
                                float2 vb = *(const float2*)(xb + k);
                                a0 = va.x; a1 = va.y; c0 = vb.x; c1 = vb.y;
                            }
                            xH[kk][seg * 2]     = pack2_split_hi(a0, a1, xL[kk][seg * 2]);
                            xH[kk][seg * 2 + 1] = pack2_split_hi(c0, c1, xL[kk][seg * 2 + 1]);
                        }
                }
                #pragma unroll
                for (int half = 0; half < 2; half++) {
                    float acc[4][4];
                    #pragma unroll
                    for (int nb = 0; nb < 4; nb++)
                        #pragma unroll
                        for (int u = 0; u < 4; u++) acc[nb][u] = 0.f;

                    #pragma unroll
                    for (int kk = 0; kk < 2; kk++) {
                        #pragma unroll
                        for (int p2 = 0; p2 < 2; p2++) {
                            int pp = half * 2 + p2;
                            int nrow = nhf * 64 + pp * 16 + b_row0;
                            uint32_t offB = SWZ64_C(nrow, 2 * kk + b_ch);
                            uint32_t bH[4], bL[4];
                            ldsm_x4(bH, smb + OF_W1TH + offB);
                            ldsm_x4(bL, smb + OF_W1TL + offB);
                            mma16816(acc[2 * p2], xH[kk], bH[0], bH[1]);
                            mma16816(acc[2 * p2], xH[kk], bL[0], bL[1]);
                            mma16816(acc[2 * p2], xL[kk], bH[0], bH[1]);
                            mma16816(acc[2 * p2 + 1], xH[kk], bH[2], bH[3]);
                            mma16816(acc[2 * p2 + 1], xH[kk], bL[2], bL[3]);
                            mma16816(acc[2 * p2 + 1], xL[kk], bH[2], bH[3]);
                        }
                    }
                    #pragma unroll
                    for (int nb = 0; nb < 4; nb++) {
                        int gnb = half * 4 + nb;
                        int c = nhf * 64 + gnb * 8 + 2 * t;
                        float bb0 = s_b1[c], bb1 = s_b1[c + 1];
                        int w = gnb * 4 + t;
                        float h00 = fmaxf(acc[nb][0] + bb0, 0.f);
                        float h01 = fmaxf(acc[nb][1] + bb1, 0.f);
                        float h10 = fmaxf(acc[nb][2] + bb0, 0.f);
                        float h11 = fmaxf(acc[nb][3] + bb1, 0.f);
                        uint32_t lo;
                        uint32_t hi = pack2_split_hi(h00, h01, lo);
                        *(uint32_t*)(smem + OF_HT + nhf * 16384 + SWZ_W(rA, w)) = hi;
                        *(uint32_t*)(smem + OF_HT + 32768 + nhf * 16384 + SWZ_W(rA, w)) = lo;
                        hi = pack2_split_hi(h10, h11, lo);
                        *(uint32_t*)(smem + OF_HT + nhf * 16384 + SWZ_W(rB, w)) = hi;
                        *(uint32_t*)(smem + OF_HT + 32768 + nhf * 16384 + SWZ_W(rB, w)) = lo;
                    }
                }
            }
            // pair barrier: h producers == consumers (warps 2*rbw, 2*rbw+1)
            asm volatile("bar.sync %0, 64;" :: "r"(rbw + 1) : "memory");

            // ---- P2: enc2 MMA: z = h @ W2 + b2 -> ZB; fold ||z||^2 into vq ----
            {
                const int a_row2 = R0w + a_roff;
                float acc2[4][4];
                #pragma unroll
                for (int nb = 0; nb < 4; nb++)
                    #pragma unroll
                    for (int u = 0; u < 4; u++) acc2[nb][u] = 0.f;

                #pragma unroll
                for (int khalf = 0; khalf < 2; khalf++) {
                    #pragma unroll
                    for (int kk = 0; kk < 4; kk++) {
                        uint32_t aH[4], aL[4];
                        uint32_t offA = SWZ_C(a_row2, 2 * kk + a_ch);
                        ldsm_x4(aH, smb + OF_HT + khalf * 16384 + offA);
                        ldsm_x4(aL, smb + OF_HT + 32768 + khalf * 16384 + offA);
                        #pragma unroll
                        for (int pp = 0; pp < 2; pp++) {
                            int nrow = nhf * 32 + pp * 16 + b_row0;
                            uint32_t offB = SWZ_C(nrow, 2 * kk + b_ch);
                            uint32_t bH[4], bL[4];
                            ldsm_x4(bH, smb + OF_W2 + khalf * 8192 + offB);
                            ldsm_x4(bL, smb + OF_W2 + 16384 + khalf * 8192 + offB);
                            mma16816(acc2[2 * pp], aH, bH[0], bH[1]);
                            mma16816(acc2[2 * pp], aH, bL[0], bL[1]);
                            mma16816(acc2[2 * pp], aL, bH[0], bH[1]);
                            mma16816(acc2[2 * pp + 1], aH, bH[2], bH[3]);
                            mma16816(acc2[2 * pp + 1], aH, bL[2], bL[3]);
                            mma16816(acc2[2 * pp + 1], aL, bH[2], bH[3]);
                        }
                    }
                }
                float z2sum = 0.f;
                int zA = zoff + rA, zB = zoff + rB;
                #pragma unroll
                for (int nb = 0; nb < 4; nb++) {
                    int c0 = nhf * 32 + nb * 8 + 2 * t;
                    int w = c0 >> 1;
                    float bb0 = s_b2[c0], bb1 = s_b2[c0 + 1];
                    float z00 = acc2[nb][0] + bb0, z01 = acc2[nb][1] + bb1;
                    float z10 = acc2[nb][2] + bb0, z11 = acc2[nb][3] + bb1;
                    z2sum = fmaf(z00, z00, fmaf(z01, z01, z2sum));
                    z2sum = fmaf(z10, z10, fmaf(z11, z11, z2sum));
                    uint32_t lo;
                    uint32_t hi = pack2_split_hi(z00, z01, lo);
                    *(uint32_t*)(smem + OF_ZBH + SWZ_W(zA, w)) = hi;
                    *(uint32_t*)(smem + OF_ZBL + SWZ_W(zA, w)) = lo;
                    hi = pack2_split_hi(z10, z11, lo);
                    *(uint32_t*)(smem + OF_ZBH + SWZ_W(zB, w)) = hi;
                    *(uint32_t*)(smem + OF_ZBL + SWZ_W(zB, w)) = lo;
                }
                vq_local += z2sum;
            }
            if (sub == 0)   // guard HT reuse by sub1's P1
                asm volatile("bar.sync %0, 64;" :: "r"(rbw + 1) : "memory");
        }
        __syncthreads();   // C

        // -------- P3: distance MMA over 16 row-blocks; warp owns 32 codes --------
        #pragma unroll 1
        for (int rb = 0; rb < 16; rb++) {
            const int a_row3 = rb * 16 + a_roff;
            uint32_t afH[2][4], afL[2][4];
            {
                uint32_t off = SWZ_C(a_row3, a_ch);
                ldsm_x4(afH[0], smb + OF_ZBH + off);
                ldsm_x4(afL[0], smb + OF_ZBL + off);
            }
            float acc3[4][4];
            #pragma unroll
            for (int nb = 0; nb < 4; nb++)
                #pragma unroll
                for (int u = 0; u < 4; u++) acc3[nb][u] = 0.f;

            #pragma unroll
            for (int kk = 0; kk < 4; kk++) {
                int cur = kk & 1;
                if (kk < 3) {
                    uint32_t off = SWZ_C(a_row3, 2 * (kk + 1) + a_ch);
                    ldsm_x4(afH[cur ^ 1], smb + OF_ZBH + off);
                    ldsm_x4(afL[cur ^ 1], smb + OF_ZBL + off);
                }
                #pragma unroll
                for (int nb = 0; nb < 4; nb++) {
                    mma16816(acc3[nb], afH[cur], bregH[nb][kk][0], bregH[nb][kk][1]);  // zH*eH
                    mma16816(acc3[nb], afL[cur], bregH[nb][kk][0], bregH[nb][kk][1]);  // zL*eH
                    mma16816(acc3[nb], afH[cur], bregL[nb][kk][0], bregL[nb][kk][1]);  // zH*eL
                }
            }
            float mA = 3.4e38f, mB = 3.4e38f; int iA = 0, iB = 0;
            #pragma unroll
            for (int nb = 0; nb < 4; nb++) {
                int c0 = warp * 32 + nb * 8 + 2 * t;
                float e0 = s_e2[c0], e1 = s_e2[c0 + 1];
                float d00 = fmaf(-2.f, acc3[nb][0], e0);
                float d01 = fmaf(-2.f, acc3[nb][1], e1);
                float d10 = fmaf(-2.f, acc3[nb][2], e0);
                float d11 = fmaf(-2.f, acc3[nb][3], e1);
                if (d00 < mA) { mA = d00; iA = c0; }
                if (d01 < mA) { mA = d01; iA = c0 + 1; }
                if (d10 < mB) { mB = d10; iB = c0; }
                if (d11 < mB) { mB = d11; iB = c0 + 1; }
            }
            #pragma unroll
            for (int off = 1; off <= 2; off <<= 1) {
                float ov = __shfl_xor_sync(0xffffffffu, mA, off);
                int   oi = __shfl_xor_sync(0xffffffffu, iA, off);
                if (ov < mA || (ov == mA && oi < iA)) { mA = ov; iA = oi; }
                ov = __shfl_xor_sync(0xffffffffu, mB, off);
                oi = __shfl_xor_sync(0xffffffffu, iB, off);
                if (ov < mB || (ov == mB && oi < iB)) { mB = ov; iB = oi; }
            }
            if (t == 0) {
                s_cd[(rb * 16 + g) * 17 + warp]     = mA;
                s_ci[(rb * 16 + g) * 17 + warp]     = (unsigned short)iA;
                s_cd[(rb * 16 + 8 + g) * 17 + warp] = mB;
                s_ci[(rb * 16 + 8 + g) * 17 + warp] = (unsigned short)iB;
            }
        }
        __syncthreads();   // D (guards CD/CI for P4; ZB free after)

        // -------- P4: per-row scan of 16 warp-candidates; vq += d_min --------
        if (tid < ITER_M) {
            const float* rowd = s_cd + tid * 17;
            const unsigned short* rowi = s_ci + tid * 17;
            float best = rowd[0];
            int   bi   = rowi[0];
            #pragma unroll
            for (int w = 1; w < EWARPS; w++) {
                float dw = rowd[w];
                if (dw < best) { best = dw; bi = rowi[w]; }
            }
            g_idx[tle * ITER_M + tid] = bi;
            vq_local += best;
        }
        // no barrier: next P1 writes HT (pair-local), next P2 writes ZB (dead);
        // CD/CI next written in P3 which is after full barrier C
    }

    // ---- reduce vq ----
    #pragma unroll
    for (int off = 16; off; off >>= 1) vq_local += __shfl_down_sync(0xffffffffu, vq_local, off);
    __syncthreads();
    float* s_red = (float*)(smem + OF_CD);
    if (lane == 0) s_red[warp] = vq_local;
    __syncthreads();
    if (tid == 0) {
        float s = 0.f;
        for (int w = 0; w < EWARPS; w++) s += s_red[w];
        g_vq_part[blockIdx.x] = s;
    }
}

// ============================================================================
// decoder table for 512 codes (exact fp32)
// ============================================================================
__global__ void k_hd(const float* __restrict__ cb,
                     const float* __restrict__ dw1, const float* __restrict__ db1)
{
    int gid = blockIdx.x * blockDim.x + threadIdx.x;
    int c = gid >> 7, j = gid & 127;
    float acc = db1[j];
    const float* q = cb + c * LAT;
    #pragma unroll 8
    for (int k = 0; k < LAT; k++) acc = fmaf(q[k], dw1[k * HID + j], acc);
    g_hd[gid] = fmaxf(acc, 0.f);
}

__global__ void k_tbl(const float* __restrict__ dw2, const float* __restrict__ db2)
{
    int gid = blockIdx.x * blockDim.x + threadIdx.x;
    int c = gid / IN_DIM, j = gid - c * IN_DIM;
    float acc = db2[j];
    const float* hd = g_hd + c * HID;
    #pragma unroll 8
    for (int k = 0; k < HID; k++) acc = fmaf(hd[k], dw2[k * IN_DIM + j], acc);
    g_tbl[gid] = acc;
}

// ============================================================================
// k_out: gather recon from table, write out, recon-loss partials
// ============================================================================
#define OUT_THREADS 512
__global__ void __launch_bounds__(OUT_THREADS)
k_out(const float* __restrict__ x, float* __restrict__ out)
{
    const int total4 = B_TOTAL * (IN_DIM / 4);
    const float4* x4 = (const float4*)x;
    float4* o4 = (float4*)out;
    const float4* t4 = (const float4*)g_tbl;

    float rec = 0.f;
    for (int f4 = blockIdx.x * OUT_THREADS + threadIdx.x; f4 < total4;
         f4 += KOUT_GRID * OUT_THREADS) {
        int row = f4 / 7;
        int w = f4 - row * 7;
        int idx = g_idx[row];
        float4 tv = t4[idx * 7 + w];
        float4 xv = x4[f4];
        o4[f4] = tv;
        float d0 = tv.x - xv.x, d1 = tv.y - xv.y, d2 = tv.z - xv.z, d3 = tv.w - xv.w;
        rec = fmaf(d0, d0, fmaf(d1, d1, fmaf(d2, d2, fmaf(d3, d3, rec))));
    }
    __shared__ float s_red[OUT_THREADS / 32];
    #pragma unroll
    for (int off = 16; off; off >>= 1) rec += __shfl_down_sync(0xffffffffu, rec, off);
    if ((threadIdx.x & 31) == 0) s_red[threadIdx.x >> 5] = rec;
    __syncthreads();
    if (threadIdx.x == 0) {
        float s = 0.f;
        for (int w = 0; w < OUT_THREADS / 32; w++) s += s_red[w];
        g_rec_part[blockIdx.x] = s;
    }
}

// ============================================================================
// finalize scalar losses
// ============================================================================
__global__ void k_final(float* __restrict__ out)
{
    if (threadIdx.x == 0) {
        double vs = 0.0, rs = 0.0;
        for (int i = 0; i < GRID1; i++) vs += (double)g_vq_part[i];
        for (int i = 0; i < KOUT_GRID; i++) rs += (double)g_rec_part[i];
        out[(long)B_TOTAL * IN_DIM]     = (float)(rs / ((double)B_TOTAL * IN_DIM));
        out[(long)B_TOTAL * IN_DIM + 1] = (float)(1.25 * vs / ((double)B_TOTAL * LAT));
    }
}

// ============================================================================
extern "C" void kernel_launch(void* const* d_in, const int* in_sizes, int n_in,
                              void* d_out, int out_size)
{
    const float* x    = (const float*)d_in[0];
    const float* ew1  = (const float*)d_in[1];
    const float* eb1  = (const float*)d_in[2];
    const float* ew2  = (const float*)d_in[3];
    const float* eb2  = (const float*)d_in[4];
    const float* cb   = (const float*)d_in[5];
    const float* dw1  = (const float*)d_in[6];
    const float* db1  = (const float*)d_in[7];
    const float* dw2  = (const float*)d_in[8];
    const float* db2  = (const float*)d_in[9];
    float* out = (float*)d_out;

    cudaFuncSetAttribute(k_encode, cudaFuncAttributeMaxDynamicSharedMemorySize, SMEM_E);

    k_hd<<<(NCODES * HID) / 256, 256>>>(cb, dw1, db1);
    k_tbl<<<(NCODES * IN_DIM) / 256, 256>>>(dw2, db2);
    k_encode<<<GRID1, ETHREADS, SMEM_E>>>(x, ew1, eb1, ew2, eb2, cb);
    k_out<<<KOUT_GRID, OUT_THREADS>>>(x, out);
    k_final<<<1, 32>>>(out);
}

// round 14
// speedup vs baseline: 1.0291x; 1.0291x over previous
#include <cuda_runtime.h>
#include <cuda_bf16.h>
#include <cstdint>

#define B_TOTAL 262144
#define IN_DIM 28
#define HID 128
#define LAT 64
#define NCODES 512
#define GRID1 148
#define TILE_M 128
#define NTILES (B_TOTAL / TILE_M)   // 2048

#define ETHREADS 512
#define EWARPS 16

// ---- k_encode smem layout (bytes) ----
#define OF_HT    0                      // 65536: h tiles HH0,HH1,HL0,HL1; CB staging at init
#define OF_ZBH   65536                  // z hi 128x128B = 16384
#define OF_ZBL   81920                  // z lo 16384
#define OF_W2    98304                  // W2H0,W2H1,W2L0,W2L1 (8K each) = 32768
#define OF_W1TH  131072                 // W1^T hi [128n][32k] 64B rows = 8192
#define OF_W1TL  139264                 // 8192
#define OF_B1    147456                 // 512
#define OF_B2    147968                 // 256
#define OF_E2    148224                 // 2048
#define OF_CD    150272                 // float[128][17] = 8704
#define OF_CI    158976                 // u16[128][17]   = 4352
#define SMEM_E   163328

// XOR swizzle, 128B rows (16B granularity)
#define SWZ_W(row, w)  ((row) * 128 + ((((w) >> 2) ^ ((row) & 7)) << 4) + ((w) & 3) * 4)
#define SWZ_C(row, ch) ((row) * 128 + ((((ch)) ^ ((row) & 7)) << 4))
// XOR swizzle, 64B rows
#define SWZ64_W(row, w)  ((row) * 64 + ((((w) >> 2) ^ (((row) >> 1) & 3)) << 4) + ((w) & 3) * 4)
#define SWZ64_C(row, ch) ((row) * 64 + ((((ch)) ^ (((row) >> 1) & 3)) << 4))

#define KOUT_GRID 592

__device__ int    g_idx[B_TOTAL];
__device__ float  g_vq_part[GRID1];
__device__ float  g_rec_part[KOUT_GRID];
__device__ float  g_hd[NCODES * HID];
__device__ float  g_tbl[NCODES * IN_DIM];

// ---------------- helpers ----------------
__device__ __forceinline__ uint32_t smem_u32_of(const void* p) {
    uint32_t a;
    asm("{ .reg .u64 t; cvta.to.shared.u64 t, %1; cvt.u32.u64 %0, t; }" : "=r"(a) : "l"(p));
    return a;
}
__device__ __forceinline__ void ldsm_x4(uint32_t* r, uint32_t addr) {
    asm volatile("ldmatrix.sync.aligned.m8n8.x4.shared.b16 {%0,%1,%2,%3}, [%4];"
        : "=r"(r[0]), "=r"(r[1]), "=r"(r[2]), "=r"(r[3]) : "r"(addr));
}
__device__ __forceinline__ void mma16816(float* d, const uint32_t* a, uint32_t b0, uint32_t b1) {
    asm volatile("mma.sync.aligned.m16n8k16.row.col.f32.bf16.bf16.f32 "
        "{%0,%1,%2,%3}, {%4,%5,%6,%7}, {%8,%9}, {%0,%1,%2,%3};"
        : "+f"(d[0]), "+f"(d[1]), "+f"(d[2]), "+f"(d[3])
        : "r"(a[0]), "r"(a[1]), "r"(a[2]), "r"(a[3]), "r"(b0), "r"(b1));
}
__device__ __forceinline__ void bf16_split(float v, __nv_bfloat16& hi, __nv_bfloat16& lo) {
    hi = __float2bfloat16(v);
    lo = __float2bfloat16(v - __bfloat162float(hi));
}
__device__ __forceinline__ uint32_t pack2_split_hi(float a, float b, uint32_t& lo_out) {
    __nv_bfloat16 ha, la, hb, lb;
    bf16_split(a, ha, la); bf16_split(b, hb, lb);
    __nv_bfloat162 ph; ph.x = ha; ph.y = hb;
    __nv_bfloat162 pl; pl.x = la; pl.y = lb;
    lo_out = *(uint32_t*)&pl;
    return *(uint32_t*)&ph;
}

// load this warp's x fragment raw values for one tile (8 float2 per lane)
__device__ __forceinline__ void load_xfrag(const float* __restrict__ x,
                                           int tle, int R0w, int g, int t,
                                           float2 xf[8])
{
    const float* xa = x + ((size_t)tle * TILE_M + R0w + g) * IN_DIM;
    const float* xb = xa + 8 * IN_DIM;
    #pragma unroll
    for (int kk = 0; kk < 2; kk++)
        #pragma unroll
        for (int seg = 0; seg < 2; seg++) {
            int k = kk * 16 + seg * 8 + 2 * t;
            int idx = kk * 4 + seg * 2;
            if (k < IN_DIM) {
                xf[idx]     = *(const float2*)(xa + k);
                xf[idx + 1] = *(const float2*)(xb + k);
            } else {
                xf[idx]     = make_float2(0.f, 0.f);
                xf[idx + 1] = make_float2(0.f, 0.f);
            }
        }
}

// ============================================================================
// K1: encoder — register-prefetched x A-frags, MMA enc1/enc2,
//     distance MMA fully register-fed (bregH+bregL), slot argmin
// ============================================================================
__global__ void __launch_bounds__(ETHREADS, 1)
k_encode(const float* __restrict__ x,
         const float* __restrict__ w1, const float* __restrict__ b1,
         const float* __restrict__ w2, const float* __restrict__ b2,
         const float* __restrict__ cb)
{
    extern __shared__ char smem[];
    const uint32_t smb = smem_u32_of(smem);

    float* s_b1 = (float*)(smem + OF_B1);
    float* s_b2 = (float*)(smem + OF_B2);
    float* s_e2 = (float*)(smem + OF_E2);
    float* s_cd = (float*)(smem + OF_CD);
    unsigned short* s_ci = (unsigned short*)(smem + OF_CI);

    const int tid = threadIdx.x;
    const int warp = tid >> 5, lane = tid & 31;

    // ---- init: weights, biases, e2; CBH staged into HT ----
    for (int i = tid; i < HID; i += ETHREADS) s_b1[i] = b1[i];
    for (int i = tid; i < LAT; i += ETHREADS) s_b2[i] = b2[i];
    for (int i = tid; i < NCODES * 32; i += ETHREADS) {      // CBH staging
        int c = i >> 5, w = i & 31;
        uint32_t lo;
        uint32_t hi = pack2_split_hi(cb[c * LAT + 2 * w], cb[c * LAT + 2 * w + 1], lo);
        *(uint32_t*)(smem + OF_HT + SWZ_W(c, w)) = hi;
        (void)lo;
    }
    for (int i = tid; i < LAT * 64; i += ETHREADS) {         // W2^T split
        int n = i >> 6, kw = i & 63;
        uint32_t lo;
        uint32_t hi = pack2_split_hi(w2[2 * kw * LAT + n], w2[(2 * kw + 1) * LAT + n], lo);
        int khalf = kw >> 5, w = kw & 31;
        *(uint32_t*)(smem + OF_W2 + khalf * 8192 + SWZ_W(n, w))         = hi;
        *(uint32_t*)(smem + OF_W2 + 16384 + khalf * 8192 + SWZ_W(n, w)) = lo;
    }
    for (int i = tid; i < HID * 14; i += ETHREADS) {         // W1^T split
        int n = i / 14, kw = i - n * 14;
        uint32_t lo;
        uint32_t hi = pack2_split_hi(w1[2 * kw * HID + n], w1[(2 * kw + 1) * HID + n], lo);
        *(uint32_t*)(smem + OF_W1TH + SWZ64_W(n, kw)) = hi;
        *(uint32_t*)(smem + OF_W1TL + SWZ64_W(n, kw)) = lo;
    }
    for (int i = tid; i < HID * 2; i += ETHREADS) {          // W1T k-pad
        int n = i >> 1, w = 14 + (i & 1);
        *(uint32_t*)(smem + OF_W1TH + SWZ64_W(n, w)) = 0;
        *(uint32_t*)(smem + OF_W1TL + SWZ64_W(n, w)) = 0;
    }
    for (int c = tid; c < NCODES; c += ETHREADS) {
        float s = 0.f;
        for (int k = 0; k < LAT; k++) { float v = cb[c * LAT + k]; s = fmaf(v, v, s); }
        s_e2[c] = s;
    }
    __syncthreads();

    // mma lane-role constants
    const int g = lane >> 2, t = lane & 3;
    const int a_roff = (lane & 7) + 8 * ((lane >> 3) & 1);
    const int a_ch   = lane >> 4;
    const int b_row0 = (lane & 7) + 8 * ((lane >> 4) & 1);
    const int b_ch   = (lane >> 3) & 1;

    // ---- codebook HI fragments -> registers ----
    uint32_t bregH[4][4][2];
    #pragma unroll
    for (int pp = 0; pp < 2; pp++)
        #pragma unroll
        for (int kk = 0; kk < 4; kk++) {
            uint32_t r4[4];
            ldsm_x4(r4, smb + OF_HT + SWZ_C(warp * 32 + pp * 16 + b_row0, 2 * kk + b_ch));
            bregH[2 * pp][kk][0] = r4[0];     bregH[2 * pp][kk][1] = r4[1];
            bregH[2 * pp + 1][kk][0] = r4[2]; bregH[2 * pp + 1][kk][1] = r4[3];
        }
    __syncthreads();
    // ---- restage CBL into HT, then codebook LO fragments -> registers ----
    for (int i = tid; i < NCODES * 32; i += ETHREADS) {
        int c = i >> 5, w = i & 31;
        uint32_t lo;
        (void)pack2_split_hi(cb[c * LAT + 2 * w], cb[c * LAT + 2 * w + 1], lo);
        *(uint32_t*)(smem + OF_HT + SWZ_W(c, w)) = lo;
    }
    __syncthreads();
    uint32_t bregL[4][4][2];
    #pragma unroll
    for (int pp = 0; pp < 2; pp++)
        #pragma unroll
        for (int kk = 0; kk < 4; kk++) {
            uint32_t r4[4];
            ldsm_x4(r4, smb + OF_HT + SWZ_C(warp * 32 + pp * 16 + b_row0, 2 * kk + b_ch));
            bregL[2 * pp][kk][0] = r4[0];     bregL[2 * pp][kk][1] = r4[1];
            bregL[2 * pp + 1][kk][0] = r4[2]; bregL[2 * pp + 1][kk][1] = r4[3];
        }
    __syncthreads();   // HT now free for h tiles

    const int rbw = warp >> 1, nhf = warp & 1;
    const int R0w = rbw * 16;
    const int rA = R0w + g, rB = rA + 8;
    float vq_local = 0.f;

    // ---- prefetch first tile's x fragment into registers ----
    float2 xf[8];
    load_xfrag(x, blockIdx.x, R0w, g, t, xf);

    for (int tle = blockIdx.x; tle < NTILES; tle += GRID1) {
        // -------- P1: split xf -> A-frags; prefetch next xf; enc1 MMA --------
        {
            uint32_t xH[2][4], xL[2][4];
            #pragma unroll
            for (int kk = 0; kk < 2; kk++)
                #pragma unroll
                for (int seg = 0; seg < 2; seg++) {
                    int idx = kk * 4 + seg * 2;
                    xH[kk][seg * 2]     = pack2_split_hi(xf[idx].x, xf[idx].y, xL[kk][seg * 2]);
                    xH[kk][seg * 2 + 1] = pack2_split_hi(xf[idx + 1].x, xf[idx + 1].y, xL[kk][seg * 2 + 1]);
                }
            // issue next tile's loads (hidden behind P1 MMA + P2 + P3)
            if (tle + GRID1 < NTILES)
                load_xfrag(x, tle + GRID1, R0w, g, t, xf);

            #pragma unroll
            for (int half = 0; half < 2; half++) {
                float acc[4][4];
                #pragma unroll
                for (int nb = 0; nb < 4; nb++)
                    #pragma unroll
                    for (int u = 0; u < 4; u++) acc[nb][u] = 0.f;

                #pragma unroll
                for (int kk = 0; kk < 2; kk++) {
                    #pragma unroll
                    for (int p2 = 0; p2 < 2; p2++) {
                        int pp = half * 2 + p2;
                        int nrow = nhf * 64 + pp * 16 + b_row0;
                        uint32_t offB = SWZ64_C(nrow, 2 * kk + b_ch);
                        uint32_t bH[4], bL[4];
                        ldsm_x4(bH, smb + OF_W1TH + offB);
                        ldsm_x4(bL, smb + OF_W1TL + offB);
                        mma16816(acc[2 * p2], xH[kk], bH[0], bH[1]);
                        mma16816(acc[2 * p2], xH[kk], bL[0], bL[1]);
                        mma16816(acc[2 * p2], xL[kk], bH[0], bH[1]);
                        mma16816(acc[2 * p2 + 1], xH[kk], bH[2], bH[3]);
                        mma16816(acc[2 * p2 + 1], xH[kk], bL[2], bL[3]);
                        mma16816(acc[2 * p2 + 1], xL[kk], bH[2], bH[3]);
                    }
                }
                #pragma unroll
                for (int nb = 0; nb < 4; nb++) {
                    int gnb = half * 4 + nb;
                    int c = nhf * 64 + gnb * 8 + 2 * t;
                    float bb0 = s_b1[c], bb1 = s_b1[c + 1];
                    int w = gnb * 4 + t;
                    float h00 = fmaxf(acc[nb][0] + bb0, 0.f);
                    float h01 = fmaxf(acc[nb][1] + bb1, 0.f);
                    float h10 = fmaxf(acc[nb][2] + bb0, 0.f);
                    float h11 = fmaxf(acc[nb][3] + bb1, 0.f);
                    uint32_t lo;
                    uint32_t hi = pack2_split_hi(h00, h01, lo);
                    *(uint32_t*)(smem + OF_HT + nhf * 16384 + SWZ_W(rA, w)) = hi;
                    *(uint32_t*)(smem + OF_HT + 32768 + nhf * 16384 + SWZ_W(rA, w)) = lo;
                    hi = pack2_split_hi(h10, h11, lo);
                    *(uint32_t*)(smem + OF_HT + nhf * 16384 + SWZ_W(rB, w)) = hi;
                    *(uint32_t*)(smem + OF_HT + 32768 + nhf * 16384 + SWZ_W(rB, w)) = lo;
                }
            }
        }
        // pair barrier: h producers == consumers (warps 2*rbw, 2*rbw+1)
        asm volatile("bar.sync %0, 64;" :: "r"(rbw + 1) : "memory");

        // -------- P2: enc2 MMA: z = h @ W2 + b2 -> ZB; fold ||z||^2 into vq --------
        {
            const int a_row2 = R0w + a_roff;
            float acc2[4][4];
            #pragma unroll
            for (int nb = 0; nb < 4; nb++)
                #pragma unroll
                for (int u = 0; u < 4; u++) acc2[nb][u] = 0.f;

            #pragma unroll
            for (int khalf = 0; khalf < 2; khalf++) {
                #pragma unroll
                for (int kk = 0; kk < 4; kk++) {
                    uint32_t aH[4], aL[4];
                    uint32_t offA = SWZ_C(a_row2, 2 * kk + a_ch);
                    ldsm_x4(aH, smb + OF_HT + khalf * 16384 + offA);
                    ldsm_x4(aL, smb + OF_HT + 32768 + khalf * 16384 + offA);
                    #pragma unroll
                    for (int pp = 0; pp < 2; pp++) {
                        int nrow = nhf * 32 + pp * 16 + b_row0;
                        uint32_t offB = SWZ_C(nrow, 2 * kk + b_ch);
                        uint32_t bH[4], bL[4];
                        ldsm_x4(bH, smb + OF_W2 + khalf * 8192 + offB);
                        ldsm_x4(bL, smb + OF_W2 + 16384 + khalf * 8192 + offB);
                        mma16816(acc2[2 * pp], aH, bH[0], bH[1]);
                        mma16816(acc2[2 * pp], aH, bL[0], bL[1]);
                        mma16816(acc2[2 * pp], aL, bH[0], bH[1]);
                        mma16816(acc2[2 * pp + 1], aH, bH[2], bH[3]);
                        mma16816(acc2[2 * pp + 1], aH, bL[2], bL[3]);
                        mma16816(acc2[2 * pp + 1], aL, bH[2], bH[3]);
                    }
                }
            }
            float z2sum = 0.f;
            #pragma unroll
            for (int nb = 0; nb < 4; nb++) {
                int c0 = nhf * 32 + nb * 8 + 2 * t;
                int w = c0 >> 1;
                float bb0 = s_b2[c0], bb1 = s_b2[c0 + 1];
                float z00 = acc2[nb][0] + bb0, z01 = acc2[nb][1] + bb1;
                float z10 = acc2[nb][2] + bb0, z11 = acc2[nb][3] + bb1;
                z2sum = fmaf(z00, z00, fmaf(z01, z01, z2sum));
                z2sum = fmaf(z10, z10, fmaf(z11, z11, z2sum));
                uint32_t lo;
                uint32_t hi = pack2_split_hi(z00, z01, lo);
                *(uint32_t*)(smem + OF_ZBH + SWZ_W(rA, w)) = hi;
                *(uint32_t*)(smem + OF_ZBL + SWZ_W(rA, w)) = lo;
                hi = pack2_split_hi(z10, z11, lo);
                *(uint32_t*)(smem + OF_ZBH + SWZ_W(rB, w)) = hi;
                *(uint32_t*)(smem + OF_ZBL + SWZ_W(rB, w)) = lo;
            }
            vq_local += z2sum;
        }
        __syncthreads();   // C

        // -------- P3: distance MMA, fully register-fed B operands --------
        #pragma unroll 1
        for (int rb = 0; rb < 8; rb++) {
            const int a_row3 = rb * 16 + a_roff;
            uint32_t afH[2][4], afL[2][4];
            {
                uint32_t off = SWZ_C(a_row3, a_ch);
                ldsm_x4(afH[0], smb + OF_ZBH + off);
                ldsm_x4(afL[0], smb + OF_ZBL + off);
            }
            float acc3[4][4];
            #pragma unroll
            for (int nb = 0; nb < 4; nb++)
                #pragma unroll
                for (int u = 0; u < 4; u++) acc3[nb][u] = 0.f;

            #pragma unroll
            for (int kk = 0; kk < 4; kk++) {
                int cur = kk & 1;
                if (kk < 3) {
                    uint32_t off = SWZ_C(a_row3, 2 * (kk + 1) + a_ch);
                    ldsm_x4(afH[cur ^ 1], smb + OF_ZBH + off);
                    ldsm_x4(afL[cur ^ 1], smb + OF_ZBL + off);
                }
                #pragma unroll
                for (int nb = 0; nb < 4; nb++) {
                    mma16816(acc3[nb], afH[cur], bregH[nb][kk][0], bregH[nb][kk][1]);  // zH*eH
                    mma16816(acc3[nb], afL[cur], bregH[nb][kk][0], bregH[nb][kk][1]);  // zL*eH
                    mma16816(acc3[nb], afH[cur], bregL[nb][kk][0], bregL[nb][kk][1]);  // zH*eL
                }
            }
            float mA = 3.4e38f, mB = 3.4e38f; int iA = 0, iB = 0;
            #pragma unroll
            for (int nb = 0; nb < 4; nb++) {
                int c0 = warp * 32 + nb * 8 + 2 * t;
                float e0 = s_e2[c0], e1 = s_e2[c0 + 1];
                float d00 = fmaf(-2.f, acc3[nb][0], e0);
                float d01 = fmaf(-2.f, acc3[nb][1], e1);
                float d10 = fmaf(-2.f, acc3[nb][2], e0);
                float d11 = fmaf(-2.f, acc3[nb][3], e1);
                if (d00 < mA) { mA = d00; iA = c0; }
                if (d01 < mA) { mA = d01; iA = c0 + 1; }
                if (d10 < mB) { mB = d10; iB = c0; }
                if (d11 < mB) { mB = d11; iB = c0 + 1; }
            }
            #pragma unroll
            for (int off = 1; off <= 2; off <<= 1) {
                float ov = __shfl_xor_sync(0xffffffffu, mA, off);
                int   oi = __shfl_xor_sync(0xffffffffu, iA, off);
                if (ov < mA || (ov == mA && oi < iA)) { mA = ov; iA = oi; }
                ov = __shfl_xor_sync(0xffffffffu, mB, off);
                oi = __shfl_xor_sync(0xffffffffu, iB, off);
                if (ov < mB || (ov == mB && oi < iB)) { mB = ov; iB = oi; }
            }
            if (t == 0) {
                s_cd[(rb * 16 + g) * 17 + warp]     = mA;
                s_ci[(rb * 16 + g) * 17 + warp]     = (unsigned short)iA;
                s_cd[(rb * 16 + 8 + g) * 17 + warp] = mB;
                s_ci[(rb * 16 + 8 + g) * 17 + warp] = (unsigned short)iB;
            }
        }
        __syncthreads();   // D

        // -------- P4: per-row scan of 16 warp-candidates; vq += d_min --------
        if (tid < TILE_M) {
            const float* rowd = s_cd + tid * 17;
            const unsigned short* rowi = s_ci + tid * 17;
            float best = rowd[0];
            int   bi   = rowi[0];
            #pragma unroll
            for (int w = 1; w < EWARPS; w++) {
                float dw = rowd[w];
                if (dw < best) { best = dw; bi = rowi[w]; }
            }
            g_idx[tle * TILE_M + tid] = bi;
            vq_local += best;
        }
        // no barrier: next P1 writes HT (pair-local, last read pre-C);
        // next P2 writes ZB (last read pre-D); CD/CI next written post-C.
    }

    // ---- reduce vq ----
    #pragma unroll
    for (int off = 16; off; off >>= 1) vq_local += __shfl_down_sync(0xffffffffu, vq_local, off);
    __syncthreads();
    float* s_red = (float*)(smem + OF_CD);
    if (lane == 0) s_red[warp] = vq_local;
    __syncthreads();
    if (tid == 0) {
        float s = 0.f;
        for (int w = 0; w < EWARPS; w++) s += s_red[w];
        g_vq_part[blockIdx.x] = s;
    }
}

// ============================================================================
// decoder table for 512 codes (exact fp32)
// ============================================================================
__global__ void k_hd(const float* __restrict__ cb,
                     const float* __restrict__ dw1, const float* __restrict__ db1)
{
    int gid = blockIdx.x * blockDim.x + threadIdx.x;
    int c = gid >> 7, j = gid & 127;
    float acc = db1[j];
    const float* q = cb + c * LAT;
    #pragma unroll 8
    for (int k = 0; k < LAT; k++) acc = fmaf(q[k], dw1[k * HID + j], acc);
    g_hd[gid] = fmaxf(acc, 0.f);
}

__global__ void k_tbl(const float* __restrict__ dw2, const float* __restrict__ db2)
{
    int gid = blockIdx.x * blockDim.x + threadIdx.x;
    int c = gid / IN_DIM, j = gid - c * IN_DIM;
    float acc = db2[j];
    const float* hd = g_hd + c * HID;
    #pragma unroll 8
    for (int k = 0; k < HID; k++) acc = fmaf(hd[k], dw2[k * IN_DIM + j], acc);
    g_tbl[gid] = acc;
}

// ============================================================================
// k_out: gather recon from table, write out, recon-loss partials
// ============================================================================
#define OUT_THREADS 512
__global__ void __launch_bounds__(OUT_THREADS)
k_out(const float* __restrict__ x, float* __restrict__ out)
{
    const int total4 = B_TOTAL * (IN_DIM / 4);
    const float4* x4 = (const float4*)x;
    float4* o4 = (float4*)out;
    const float4* t4 = (const float4*)g_tbl;

    float rec = 0.f;
    for (int f4 = blockIdx.x * OUT_THREADS + threadIdx.x; f4 < total4;
         f4 += KOUT_GRID * OUT_THREADS) {
        int row = f4 / 7;
        int w = f4 - row * 7;
        int idx = g_idx[row];
        float4 tv = t4[idx * 7 + w];
        float4 xv = x4[f4];
        o4[f4] = tv;
        float d0 = tv.x - xv.x, d1 = tv.y - xv.y, d2 = tv.z - xv.z, d3 = tv.w - xv.w;
        rec = fmaf(d0, d0, fmaf(d1, d1, fmaf(d2, d2, fmaf(d3, d3, rec))));
    }
    __shared__ float s_red[OUT_THREADS / 32];
    #pragma unroll
    for (int off = 16; off; off >>= 1) rec += __shfl_down_sync(0xffffffffu, rec, off);
    if ((threadIdx.x & 31) == 0) s_red[threadIdx.x >> 5] = rec;
    __syncthreads();
    if (threadIdx.x == 0) {
        float s = 0.f;
        for (int w = 0; w < OUT_THREADS / 32; w++) s += s_red[w];
        g_rec_part[blockIdx.x] = s;
    }
}

// ============================================================================
// finalize scalar losses
// ============================================================================
__global__ void k_final(float* __restrict__ out)
{
    if (threadIdx.x == 0) {
        double vs = 0.0, rs = 0.0;
        for (int i = 0; i < GRID1; i++) vs += (double)g_vq_part[i];
        for (int i = 0; i < KOUT_GRID; i++) rs += (double)g_rec_part[i];
        out[(long)B_TOTAL * IN_DIM]     = (float)(rs / ((double)B_TOTAL * IN_DIM));
        out[(long)B_TOTAL * IN_DIM + 1] = (float)(1.25 * vs / ((double)B_TOTAL * LAT));
    }
}

// ============================================================================
extern "C" void kernel_launch(void* const* d_in, const int* in_sizes, int n_in,
                              void* d_out, int out_size)
{
    const float* x    = (const float*)d_in[0];
    const float* ew1  = (const float*)d_in[1];
    const float* eb1  = (const float*)d_in[2];
    const float* ew2  = (const float*)d_in[3];
    const float* eb2  = (const float*)d_in[4];
    const float* cb   = (const float*)d_in[5];
    const float* dw1  = (const float*)d_in[6];
    const float* db1  = (const float*)d_in[7];
    const float* dw2  = (const float*)d_in[8];
    const float* db2  = (const float*)d_in[9];
    float* out = (float*)d_out;

    cudaFuncSetAttribute(k_encode, cudaFuncAttributeMaxDynamicSharedMemorySize, SMEM_E);

    k_hd<<<(NCODES * HID) / 256, 256>>>(cb, dw1, db1);
    k_tbl<<<(NCODES * IN_DIM) / 256, 256>>>(dw2, db2);
    k_encode<<<GRID1, ETHREADS, SMEM_E>>>(x, ew1, eb1, ew2, eb2, cb);
    k_out<<<KOUT_GRID, OUT_THREADS>>>(x, out);
    k_final<<<1, 32>>>(out);
}

// round 15
// speedup vs baseline: 1.1405x; 1.1083x over previous
#include <cuda_runtime.h>
#include <cuda_bf16.h>
#include <cstdint>

#define B_TOTAL 262144
#define IN_DIM 28
#define HID 128
#define LAT 64
#define NCODES 512
#define GRID1 148
#define TILE_M 128
#define NTILES (B_TOTAL / TILE_M)   // 2048

#define ETHREADS 512
#define EWARPS 16

// ---- k_encode smem layout (bytes) ----
#define OF_HT    0                      // 65536: h tiles HH0,HH1,HL0,HL1; CB staging at init
#define OF_ZBH   65536                  // z hi 128x128B = 16384
#define OF_ZBL   81920                  // z lo 16384
#define OF_W2    98304                  // W2H0,W2H1,W2L0,W2L1 (8K each) = 32768
#define OF_W1TH  131072                 // W1^T hi [128n][32k] 64B rows = 8192
#define OF_W1TL  139264                 // 8192
#define OF_B1    147456                 // 512
#define OF_B2    147968                 // 256
#define OF_E2    148224                 // 2048
#define OF_CD    150272                 // float[128][17] = 8704
#define OF_CI    158976                 // u16[128][17]   = 4352
#define SMEM_E   163328

// XOR swizzle, 128B rows (16B granularity)
#define SWZ_W(row, w)  ((row) * 128 + ((((w) >> 2) ^ ((row) & 7)) << 4) + ((w) & 3) * 4)
#define SWZ_C(row, ch) ((row) * 128 + ((((ch)) ^ ((row) & 7)) << 4))
// XOR swizzle, 64B rows
#define SWZ64_W(row, w)  ((row) * 64 + ((((w) >> 2) ^ (((row) >> 1) & 3)) << 4) + ((w) & 3) * 4)
#define SWZ64_C(row, ch) ((row) * 64 + ((((ch)) ^ (((row) >> 1) & 3)) << 4))

__device__ float  g_vq_part[GRID1];
__device__ float  g_rec_part[GRID1];
__device__ float  g_hd[NCODES * HID];
__device__ float  g_tbl[NCODES * IN_DIM];

// ---------------- helpers ----------------
__device__ __forceinline__ uint32_t smem_u32_of(const void* p) {
    uint32_t a;
    asm("{ .reg .u64 t; cvta.to.shared.u64 t, %1; cvt.u32.u64 %0, t; }" : "=r"(a) : "l"(p));
    return a;
}
__device__ __forceinline__ void ldsm_x4(uint32_t* r, uint32_t addr) {
    asm volatile("ldmatrix.sync.aligned.m8n8.x4.shared.b16 {%0,%1,%2,%3}, [%4];"
        : "=r"(r[0]), "=r"(r[1]), "=r"(r[2]), "=r"(r[3]) : "r"(addr));
}
__device__ __forceinline__ void mma16816(float* d, const uint32_t* a, uint32_t b0, uint32_t b1) {
    asm volatile("mma.sync.aligned.m16n8k16.row.col.f32.bf16.bf16.f32 "
        "{%0,%1,%2,%3}, {%4,%5,%6,%7}, {%8,%9}, {%0,%1,%2,%3};"
        : "+f"(d[0]), "+f"(d[1]), "+f"(d[2]), "+f"(d[3])
        : "r"(a[0]), "r"(a[1]), "r"(a[2]), "r"(a[3]), "r"(b0), "r"(b1));
}
// split two floats into packed-bf16 hi + packed-bf16 lo (residual), rn rounding.
// PTX cvt d,a,b puts a in HIGH half, b in LOW half -> pass (b_val, a_val).
__device__ __forceinline__ uint32_t pack2_split_hi(float a, float b, uint32_t& lo_out) {
    uint32_t hi;
    asm("cvt.rn.bf16x2.f32 %0, %1, %2;" : "=r"(hi) : "f"(b), "f"(a));
    float ha = __uint_as_float(hi << 16);
    float hb = __uint_as_float(hi & 0xffff0000u);
    float la = a - ha, lb = b - hb;
    asm("cvt.rn.bf16x2.f32 %0, %1, %2;" : "=r"(lo_out) : "f"(lb), "f"(la));
    return hi;
}

// load this warp's x fragment raw values for one tile (8 float2 per lane)
__device__ __forceinline__ void load_xfrag(const float* __restrict__ x,
                                           int tle, int R0w, int g, int t,
                                           float2 xf[8])
{
    const float* xa = x + ((size_t)tle * TILE_M + R0w + g) * IN_DIM;
    const float* xb = xa + 8 * IN_DIM;
    #pragma unroll
    for (int kk = 0; kk < 2; kk++)
        #pragma unroll
        for (int seg = 0; seg < 2; seg++) {
            int k = kk * 16 + seg * 8 + 2 * t;
            int idx = kk * 4 + seg * 2;
            if (k < IN_DIM) {
                xf[idx]     = *(const float2*)(xa + k);
                xf[idx + 1] = *(const float2*)(xb + k);
            } else {
                xf[idx]     = make_float2(0.f, 0.f);
                xf[idx + 1] = make_float2(0.f, 0.f);
            }
        }
}

// ============================================================================
// K1: encoder + fused recon — register-prefetched x A-frags, MMA enc1/enc2,
//     register-fed distance MMA, slot argmin, in-place table gather + out
// ============================================================================
__global__ void __launch_bounds__(ETHREADS, 1)
k_encode(const float* __restrict__ x,
         const float* __restrict__ w1, const float* __restrict__ b1,
         const float* __restrict__ w2, const float* __restrict__ b2,
         const float* __restrict__ cb, float* __restrict__ out)
{
    extern __shared__ char smem[];
    const uint32_t smb = smem_u32_of(smem);

    float* s_b1 = (float*)(smem + OF_B1);
    float* s_b2 = (float*)(smem + OF_B2);
    float* s_e2 = (float*)(smem + OF_E2);
    float* s_cd = (float*)(smem + OF_CD);
    unsigned short* s_ci = (unsigned short*)(smem + OF_CI);

    const int tid = threadIdx.x;
    const int warp = tid >> 5, lane = tid & 31;

    // ---- init: weights, biases, e2; CBH staged into HT ----
    for (int i = tid; i < HID; i += ETHREADS) s_b1[i] = b1[i];
    for (int i = tid; i < LAT; i += ETHREADS) s_b2[i] = b2[i];
    for (int i = tid; i < NCODES * 32; i += ETHREADS) {      // CBH staging
        int c = i >> 5, w = i & 31;
        uint32_t lo;
        uint32_t hi = pack2_split_hi(cb[c * LAT + 2 * w], cb[c * LAT + 2 * w + 1], lo);
        *(uint32_t*)(smem + OF_HT + SWZ_W(c, w)) = hi;
        (void)lo;
    }
    for (int i = tid; i < LAT * 64; i += ETHREADS) {         // W2^T split
        int n = i >> 6, kw = i & 63;
        uint32_t lo;
        uint32_t hi = pack2_split_hi(w2[2 * kw * LAT + n], w2[(2 * kw + 1) * LAT + n], lo);
        int khalf = kw >> 5, w = kw & 31;
        *(uint32_t*)(smem + OF_W2 + khalf * 8192 + SWZ_W(n, w))         = hi;
        *(uint32_t*)(smem + OF_W2 + 16384 + khalf * 8192 + SWZ_W(n, w)) = lo;
    }
    for (int i = tid; i < HID * 14; i += ETHREADS) {         // W1^T split
        int n = i / 14, kw = i - n * 14;
        uint32_t lo;
        uint32_t hi = pack2_split_hi(w1[2 * kw * HID + n], w1[(2 * kw + 1) * HID + n], lo);
        *(uint32_t*)(smem + OF_W1TH + SWZ64_W(n, kw)) = hi;
        *(uint32_t*)(smem + OF_W1TL + SWZ64_W(n, kw)) = lo;
    }
    for (int i = tid; i < HID * 2; i += ETHREADS) {          // W1T k-pad
        int n = i >> 1, w = 14 + (i & 1);
        *(uint32_t*)(smem + OF_W1TH + SWZ64_W(n, w)) = 0;
        *(uint32_t*)(smem + OF_W1TL + SWZ64_W(n, w)) = 0;
    }
    for (int c = tid; c < NCODES; c += ETHREADS) {
        float s = 0.f;
        for (int k = 0; k < LAT; k++) { float v = cb[c * LAT + k]; s = fmaf(v, v, s); }
        s_e2[c] = s;
    }
    __syncthreads();

    // mma lane-role constants
    const int g = lane >> 2, t = lane & 3;
    const int a_roff = (lane & 7) + 8 * ((lane >> 3) & 1);
    const int a_ch   = lane >> 4;
    const int b_row0 = (lane & 7) + 8 * ((lane >> 4) & 1);
    const int b_ch   = (lane >> 3) & 1;

    // ---- codebook HI fragments -> registers ----
    uint32_t bregH[4][4][2];
    #pragma unroll
    for (int pp = 0; pp < 2; pp++)
        #pragma unroll
        for (int kk = 0; kk < 4; kk++) {
            uint32_t r4[4];
            ldsm_x4(r4, smb + OF_HT + SWZ_C(warp * 32 + pp * 16 + b_row0, 2 * kk + b_ch));
            bregH[2 * pp][kk][0] = r4[0];     bregH[2 * pp][kk][1] = r4[1];
            bregH[2 * pp + 1][kk][0] = r4[2]; bregH[2 * pp + 1][kk][1] = r4[3];
        }
    __syncthreads();
    // ---- restage CBL into HT, then codebook LO fragments -> registers ----
    for (int i = tid; i < NCODES * 32; i += ETHREADS) {
        int c = i >> 5, w = i & 31;
        uint32_t lo;
        (void)pack2_split_hi(cb[c * LAT + 2 * w], cb[c * LAT + 2 * w + 1], lo);
        *(uint32_t*)(smem + OF_HT + SWZ_W(c, w)) = lo;
    }
    __syncthreads();
    uint32_t bregL[4][4][2];
    #pragma unroll
    for (int pp = 0; pp < 2; pp++)
        #pragma unroll
        for (int kk = 0; kk < 4; kk++) {
            uint32_t r4[4];
            ldsm_x4(r4, smb + OF_HT + SWZ_C(warp * 32 + pp * 16 + b_row0, 2 * kk + b_ch));
            bregL[2 * pp][kk][0] = r4[0];     bregL[2 * pp][kk][1] = r4[1];
            bregL[2 * pp + 1][kk][0] = r4[2]; bregL[2 * pp + 1][kk][1] = r4[3];
        }
    __syncthreads();   // HT now free for h tiles

    const int rbw = warp >> 1, nhf = warp & 1;
    const int R0w = rbw * 16;
    const int rA = R0w + g, rB = rA + 8;
    float vq_local = 0.f, rec_local = 0.f;

    // ---- prefetch first tile's x fragment into registers ----
    float2 xf[8];
    load_xfrag(x, blockIdx.x, R0w, g, t, xf);

    for (int tle = blockIdx.x; tle < NTILES; tle += GRID1) {
        // -------- P1: split xf -> A-frags; prefetch next xf; enc1 MMA --------
        {
            uint32_t xH[2][4], xL[2][4];
            #pragma unroll
            for (int kk = 0; kk < 2; kk++)
                #pragma unroll
                for (int seg = 0; seg < 2; seg++) {
                    int idx = kk * 4 + seg * 2;
                    xH[kk][seg * 2]     = pack2_split_hi(xf[idx].x, xf[idx].y, xL[kk][seg * 2]);
                    xH[kk][seg * 2 + 1] = pack2_split_hi(xf[idx + 1].x, xf[idx + 1].y, xL[kk][seg * 2 + 1]);
                }
            // issue next tile's loads (hidden behind P1 MMA + P2 + P3)
            if (tle + GRID1 < NTILES)
                load_xfrag(x, tle + GRID1, R0w, g, t, xf);

            #pragma unroll
            for (int half = 0; half < 2; half++) {
                float acc[4][4];
                #pragma unroll
                for (int nb = 0; nb < 4; nb++)
                    #pragma unroll
                    for (int u = 0; u < 4; u++) acc[nb][u] = 0.f;

                #pragma unroll
                for (int kk = 0; kk < 2; kk++) {
                    #pragma unroll
                    for (int p2 = 0; p2 < 2; p2++) {
                        int pp = half * 2 + p2;
                        int nrow = nhf * 64 + pp * 16 + b_row0;
                        uint32_t offB = SWZ64_C(nrow, 2 * kk + b_ch);
                        uint32_t bH[4], bL[4];
                        ldsm_x4(bH, smb + OF_W1TH + offB);
                        ldsm_x4(bL, smb + OF_W1TL + offB);
                        mma16816(acc[2 * p2], xH[kk], bH[0], bH[1]);
                        mma16816(acc[2 * p2], xH[kk], bL[0], bL[1]);
                        mma16816(acc[2 * p2], xL[kk], bH[0], bH[1]);
                        mma16816(acc[2 * p2 + 1], xH[kk], bH[2], bH[3]);
                        mma16816(acc[2 * p2 + 1], xH[kk], bL[2], bL[3]);
                        mma16816(acc[2 * p2 + 1], xL[kk], bH[2], bH[3]);
                    }
                }
                #pragma unroll
                for (int nb = 0; nb < 4; nb++) {
                    int gnb = half * 4 + nb;
                    int c = nhf * 64 + gnb * 8 + 2 * t;
                    float bb0 = s_b1[c], bb1 = s_b1[c + 1];
                    int w = gnb * 4 + t;
                    float h00 = fmaxf(acc[nb][0] + bb0, 0.f);
                    float h01 = fmaxf(acc[nb][1] + bb1, 0.f);
                    float h10 = fmaxf(acc[nb][2] + bb0, 0.f);
                    float h11 = fmaxf(acc[nb][3] + bb1, 0.f);
                    uint32_t lo;
                    uint32_t hi = pack2_split_hi(h00, h01, lo);
                    *(uint32_t*)(smem + OF_HT + nhf * 16384 + SWZ_W(rA, w)) = hi;
                    *(uint32_t*)(smem + OF_HT + 32768 + nhf * 16384 + SWZ_W(rA, w)) = lo;
                    hi = pack2_split_hi(h10, h11, lo);
                    *(uint32_t*)(smem + OF_HT + nhf * 16384 + SWZ_W(rB, w)) = hi;
                    *(uint32_t*)(smem + OF_HT + 32768 + nhf * 16384 + SWZ_W(rB, w)) = lo;
                }
            }
        }
        // pair barrier: h producers == consumers (warps 2*rbw, 2*rbw+1)
        asm volatile("bar.sync %0, 64;" :: "r"(rbw + 1) : "memory");

        // -------- P2: enc2 MMA: z = h @ W2 + b2 -> ZB; fold ||z||^2 into vq --------
        {
            const int a_row2 = R0w + a_roff;
            float acc2[4][4];
            #pragma unroll
            for (int nb = 0; nb < 4; nb++)
                #pragma unroll
                for (int u = 0; u < 4; u++) acc2[nb][u] = 0.f;

            #pragma unroll
            for (int khalf = 0; khalf < 2; khalf++) {
                #pragma unroll
                for (int kk = 0; kk < 4; kk++) {
                    uint32_t aH[4], aL[4];
                    uint32_t offA = SWZ_C(a_row2, 2 * kk + a_ch);
                    ldsm_x4(aH, smb + OF_HT + khalf * 16384 + offA);
                    ldsm_x4(aL, smb + OF_HT + 32768 + khalf * 16384 + offA);
                    #pragma unroll
                    for (int pp = 0; pp < 2; pp++) {
                        int nrow = nhf * 32 + pp * 16 + b_row0;
                        uint32_t offB = SWZ_C(nrow, 2 * kk + b_ch);
                        uint32_t bH[4], bL[4];
                        ldsm_x4(bH, smb + OF_W2 + khalf * 8192 + offB);
                        ldsm_x4(bL, smb + OF_W2 + 16384 + khalf * 8192 + offB);
                        mma16816(acc2[2 * pp], aH, bH[0], bH[1]);
                        mma16816(acc2[2 * pp], aH, bL[0], bL[1]);
                        mma16816(acc2[2 * pp], aL, bH[0], bH[1]);
                        mma16816(acc2[2 * pp + 1], aH, bH[2], bH[3]);
                        mma16816(acc2[2 * pp + 1], aH, bL[2], bL[3]);
                        mma16816(acc2[2 * pp + 1], aL, bH[2], bH[3]);
                    }
                }
            }
            float z2sum = 0.f;
            #pragma unroll
            for (int nb = 0; nb < 4; nb++) {
                int c0 = nhf * 32 + nb * 8 + 2 * t;
                int w = c0 >> 1;
                float bb0 = s_b2[c0], bb1 = s_b2[c0 + 1];
                float z00 = acc2[nb][0] + bb0, z01 = acc2[nb][1] + bb1;
                float z10 = acc2[nb][2] + bb0, z11 = acc2[nb][3] + bb1;
                z2sum = fmaf(z00, z00, fmaf(z01, z01, z2sum));
                z2sum = fmaf(z10, z10, fmaf(z11, z11, z2sum));
                uint32_t lo;
                uint32_t hi = pack2_split_hi(z00, z01, lo);
                *(uint32_t*)(smem + OF_ZBH + SWZ_W(rA, w)) = hi;
                *(uint32_t*)(smem + OF_ZBL + SWZ_W(rA, w)) = lo;
                hi = pack2_split_hi(z10, z11, lo);
                *(uint32_t*)(smem + OF_ZBH + SWZ_W(rB, w)) = hi;
                *(uint32_t*)(smem + OF_ZBL + SWZ_W(rB, w)) = lo;
            }
            vq_local += z2sum;
        }
        __syncthreads();   // C

        // -------- P3: distance MMA, fully register-fed B operands --------
        #pragma unroll 1
        for (int rb = 0; rb < 8; rb++) {
            const int a_row3 = rb * 16 + a_roff;
            uint32_t afH[2][4], afL[2][4];
            {
                uint32_t off = SWZ_C(a_row3, a_ch);
                ldsm_x4(afH[0], smb + OF_ZBH + off);
                ldsm_x4(afL[0], smb + OF_ZBL + off);
            }
            float acc3[4][4];
            #pragma unroll
            for (int nb = 0; nb < 4; nb++)
                #pragma unroll
                for (int u = 0; u < 4; u++) acc3[nb][u] = 0.f;

            #pragma unroll
            for (int kk = 0; kk < 4; kk++) {
                int cur = kk & 1;
                if (kk < 3) {
                    uint32_t off = SWZ_C(a_row3, 2 * (kk + 1) + a_ch);
                    ldsm_x4(afH[cur ^ 1], smb + OF_ZBH + off);
                    ldsm_x4(afL[cur ^ 1], smb + OF_ZBL + off);
                }
                #pragma unroll
                for (int nb = 0; nb < 4; nb++) {
                    mma16816(acc3[nb], afH[cur], bregH[nb][kk][0], bregH[nb][kk][1]);  // zH*eH
                    mma16816(acc3[nb], afL[cur], bregH[nb][kk][0], bregH[nb][kk][1]);  // zL*eH
                    mma16816(acc3[nb], afH[cur], bregL[nb][kk][0], bregL[nb][kk][1]);  // zH*eL
                }
            }
            float mA = 3.4e38f, mB = 3.4e38f; int iA = 0, iB = 0;
            #pragma unroll
            for (int nb = 0; nb < 4; nb++) {
                int c0 = warp * 32 + nb * 8 + 2 * t;
                float e0 = s_e2[c0], e1 = s_e2[c0 + 1];
                float d00 = fmaf(-2.f, acc3[nb][0], e0);
                float d01 = fmaf(-2.f, acc3[nb][1], e1);
                float d10 = fmaf(-2.f, acc3[nb][2], e0);
                float d11 = fmaf(-2.f, acc3[nb][3], e1);
                if (d00 < mA) { mA = d00; iA = c0; }
                if (d01 < mA) { mA = d01; iA = c0 + 1; }
                if (d10 < mB) { mB = d10; iB = c0; }
                if (d11 < mB) { mB = d11; iB = c0 + 1; }
            }
            #pragma unroll
            for (int off = 1; off <= 2; off <<= 1) {
                float ov = __shfl_xor_sync(0xffffffffu, mA, off);
                int   oi = __shfl_xor_sync(0xffffffffu, iA, off);
                if (ov < mA || (ov == mA && oi < iA)) { mA = ov; iA = oi; }
                ov = __shfl_xor_sync(0xffffffffu, mB, off);
                oi = __shfl_xor_sync(0xffffffffu, iB, off);
                if (ov < mB || (ov == mB && oi < iB)) { mB = ov; iB = oi; }
            }
            if (t == 0) {
                s_cd[(rb * 16 + g) * 17 + warp]     = mA;
                s_ci[(rb * 16 + g) * 17 + warp]     = (unsigned short)iA;
                s_cd[(rb * 16 + 8 + g) * 17 + warp] = mB;
                s_ci[(rb * 16 + 8 + g) * 17 + warp] = (unsigned short)iB;
            }
        }
        __syncthreads();   // D

        // -------- P4: scan candidates; fused recon gather + out + rec loss --------
        if (tid < TILE_M) {
            const float* rowd = s_cd + tid * 17;
            const unsigned short* rowi = s_ci + tid * 17;
            float best = rowd[0];
            int   bi   = rowi[0];
            #pragma unroll
            for (int w = 1; w < EWARPS; w++) {
                float dw = rowd[w];
                if (dw < best) { best = dw; bi = rowi[w]; }
            }
            vq_local += best;

            // recon = g_tbl[bi]; write out; accumulate recon loss
            const float4* trow = (const float4*)(g_tbl + bi * IN_DIM);
            const float4* xrow = (const float4*)(x + ((size_t)tle * TILE_M + tid) * IN_DIM);
            float4* orow = (float4*)(out + ((size_t)tle * TILE_M + tid) * IN_DIM);
            #pragma unroll
            for (int w = 0; w < 7; w++) {
                float4 tv = trow[w];
                float4 xv = xrow[w];
                orow[w] = tv;
                float d0 = tv.x - xv.x, d1 = tv.y - xv.y;
                float d2 = tv.z - xv.z, d3 = tv.w - xv.w;
                rec_local = fmaf(d0, d0, fmaf(d1, d1, fmaf(d2, d2, fmaf(d3, d3, rec_local))));
            }
        }
        // no barrier: next P1 writes HT (pair-local, last read pre-C);
        // next P2 writes ZB (last read pre-D); CD/CI next written post-C.
    }

    // ---- reduce vq + rec ----
    #pragma unroll
    for (int off = 16; off; off >>= 1) {
        vq_local  += __shfl_down_sync(0xffffffffu, vq_local, off);
        rec_local += __shfl_down_sync(0xffffffffu, rec_local, off);
    }
    __syncthreads();
    float* s_red = (float*)(smem + OF_CD);
    if (lane == 0) { s_red[warp] = vq_local; s_red[EWARPS + warp] = rec_local; }
    __syncthreads();
    if (tid == 0) {
        float sv = 0.f, sr = 0.f;
        for (int w = 0; w < EWARPS; w++) { sv += s_red[w]; sr += s_red[EWARPS + w]; }
        g_vq_part[blockIdx.x]  = sv;
        g_rec_part[blockIdx.x] = sr;
    }
}

// ============================================================================
// decoder table for 512 codes (exact fp32)
// ============================================================================
__global__ void k_hd(const float* __restrict__ cb,
                     const float* __restrict__ dw1, const float* __restrict__ db1)
{
    int gid = blockIdx.x * blockDim.x + threadIdx.x;
    int c = gid >> 7, j = gid & 127;
    float acc = db1[j];
    const float* q = cb + c * LAT;
    #pragma unroll 8
    for (int k = 0; k < LAT; k++) acc = fmaf(q[k], dw1[k * HID + j], acc);
    g_hd[gid] = fmaxf(acc, 0.f);
}

__global__ void k_tbl(const float* __restrict__ dw2, const float* __restrict__ db2)
{
    int gid = blockIdx.x * blockDim.x + threadIdx.x;
    int c = gid / IN_DIM, j = gid - c * IN_DIM;
    float acc = db2[j];
    const float* hd = g_hd + c * HID;
    #pragma unroll 8
    for (int k = 0; k < HID; k++) acc = fmaf(hd[k], dw2[k * IN_DIM + j], acc);
    g_tbl[gid] = acc;
}

// ============================================================================
// finalize scalar losses
// ============================================================================
__global__ void k_final(float* __restrict__ out)
{
    if (threadIdx.x == 0) {
        double vs = 0.0, rs = 0.0;
        for (int i = 0; i < GRID1; i++) { vs += (double)g_vq_part[i]; rs += (double)g_rec_part[i]; }
        out[(long)B_TOTAL * IN_DIM]     = (float)(rs / ((double)B_TOTAL * IN_DIM));
        out[(long)B_TOTAL * IN_DIM + 1] = (float)(1.25 * vs / ((double)B_TOTAL * LAT));
    }
}

// ============================================================================
extern "C" void kernel_launch(void* const* d_in, const int* in_sizes, int n_in,
                              void* d_out, int out_size)
{
    const float* x    = (const float*)d_in[0];
    const float* ew1  = (const float*)d_in[1];
    const float* eb1  = (const float*)d_in[2];
    const float* ew2  = (const float*)d_in[3];
    const float* eb2  = (const float*)d_in[4];
    const float* cb   = (const float*)d_in[5];
    const float* dw1  = (const float*)d_in[6];
    const float* db1  = (const float*)d_in[7];
    const float* dw2  = (const float*)d_in[8];
    const float* db2  = (const float*)d_in[9];
    float* out = (float*)d_out;

    cudaFuncSetAttribute(k_encode, cudaFuncAttributeMaxDynamicSharedMemorySize, SMEM_E);

    k_hd<<<(NCODES * HID) / 256, 256>>>(cb, dw1, db1);
    k_tbl<<<(NCODES * IN_DIM) / 256, 256>>>(dw2, db2);
    k_encode<<<GRID1, ETHREADS, SMEM_E>>>(x, ew1, eb1, ew2, eb2, cb, out);
    k_final<<<1, 32>>>(out);
}

// round 16
// speedup vs baseline: 1.2231x; 1.0725x over previous
#include <cuda_runtime.h>
#include <cuda_bf16.h>
#include <cstdint>

#define B_TOTAL 262144
#define IN_DIM 28
#define HID 128
#define LAT 64
#define NCODES 512
#define GRID1 148
#define TILE_M 128
#define NTILES (B_TOTAL / TILE_M)   // 2048

#define ETHREADS 512
#define EWARPS 16

// ---- k_encode smem layout (bytes) ----
#define OF_HT    0                      // 65536: h tiles HH0,HH1,HL0,HL1; CB staging at init
#define OF_ZBH   65536                  // z hi 128x128B = 16384
#define OF_ZBL   81920                  // z lo 16384
#define OF_W2    98304                  // W2H0,W2H1,W2L0,W2L1 (8K each) = 32768
#define OF_W1TH  131072                 // W1^T hi [128n][32k] 64B rows = 8192
#define OF_W1TL  139264                 // 8192
#define OF_B1    147456                 // 512
#define OF_B2    147968                 // 256
#define OF_E2    148224                 // 2048
#define OF_CD    150272                 // float[128][17] = 8704
#define OF_CI    158976                 // u16[128][17]   = 4352
#define SMEM_E   163328

// XOR swizzle, 128B rows (16B granularity)
#define SWZ_W(row, w)  ((row) * 128 + ((((w) >> 2) ^ ((row) & 7)) << 4) + ((w) & 3) * 4)
#define SWZ_C(row, ch) ((row) * 128 + ((((ch)) ^ ((row) & 7)) << 4))
// XOR swizzle, 64B rows
#define SWZ64_W(row, w)  ((row) * 64 + ((((w) >> 2) ^ (((row) >> 1) & 3)) << 4) + ((w) & 3) * 4)
#define SWZ64_C(row, ch) ((row) * 64 + ((((ch)) ^ (((row) >> 1) & 3)) << 4))

__device__ float  g_vq_part[GRID1];
__device__ float  g_rec_part[GRID1];
__device__ float  g_hd[NCODES * HID];
__device__ float  g_tbl[NCODES * IN_DIM];

// ---------------- helpers ----------------
__device__ __forceinline__ uint32_t smem_u32_of(const void* p) {
    uint32_t a;
    asm("{ .reg .u64 t; cvta.to.shared.u64 t, %1; cvt.u32.u64 %0, t; }" : "=r"(a) : "l"(p));
    return a;
}
__device__ __forceinline__ void ldsm_x4(uint32_t* r, uint32_t addr) {
    asm volatile("ldmatrix.sync.aligned.m8n8.x4.shared.b16 {%0,%1,%2,%3}, [%4];"
        : "=r"(r[0]), "=r"(r[1]), "=r"(r[2]), "=r"(r[3]) : "r"(addr));
}
__device__ __forceinline__ void mma16816(float* d, const uint32_t* a, uint32_t b0, uint32_t b1) {
    asm volatile("mma.sync.aligned.m16n8k16.row.col.f32.bf16.bf16.f32 "
        "{%0,%1,%2,%3}, {%4,%5,%6,%7}, {%8,%9}, {%0,%1,%2,%3};"
        : "+f"(d[0]), "+f"(d[1]), "+f"(d[2]), "+f"(d[3])
        : "r"(a[0]), "r"(a[1]), "r"(a[2]), "r"(a[3]), "r"(b0), "r"(b1));
}
// split two floats into packed-bf16 hi + packed-bf16 lo (residual), rn rounding.
// PTX cvt d,a,b puts a in HIGH half, b in LOW half -> pass (b_val, a_val).
__device__ __forceinline__ uint32_t pack2_split_hi(float a, float b, uint32_t& lo_out) {
    uint32_t hi;
    asm("cvt.rn.bf16x2.f32 %0, %1, %2;" : "=r"(hi) : "f"(b), "f"(a));
    float ha = __uint_as_float(hi << 16);
    float hb = __uint_as_float(hi & 0xffff0000u);
    float la = a - ha, lb = b - hb;
    asm("cvt.rn.bf16x2.f32 %0, %1, %2;" : "=r"(lo_out) : "f"(lb), "f"(la));
    return hi;
}

// load this warp's x fragment raw values for one tile (8 float2 per lane)
__device__ __forceinline__ void load_xfrag(const float* __restrict__ x,
                                           int tle, int R0w, int g, int t,
                                           float2 xf[8])
{
    const float* xa = x + ((size_t)tle * TILE_M + R0w + g) * IN_DIM;
    const float* xb = xa + 8 * IN_DIM;
    #pragma unroll
    for (int kk = 0; kk < 2; kk++)
        #pragma unroll
        for (int seg = 0; seg < 2; seg++) {
            int k = kk * 16 + seg * 8 + 2 * t;
            int idx = kk * 4 + seg * 2;
            if (k < IN_DIM) {
                xf[idx]     = *(const float2*)(xa + k);
                xf[idx + 1] = *(const float2*)(xb + k);
            } else {
                xf[idx]     = make_float2(0.f, 0.f);
                xf[idx + 1] = make_float2(0.f, 0.f);
            }
        }
}

// ============================================================================
// K1: encoder + fused recon — register-prefetched x A-frags, MMA enc1/enc2,
//     register-fed distance MMA, slot argmin, in-place table gather + out
// ============================================================================
__global__ void __launch_bounds__(ETHREADS, 1)
k_encode(const float* __restrict__ x,
         const float* __restrict__ w1, const float* __restrict__ b1,
         const float* __restrict__ w2, const float* __restrict__ b2,
         const float* __restrict__ cb, float* __restrict__ out)
{
    extern __shared__ char smem[];
    const uint32_t smb = smem_u32_of(smem);

    float* s_b1 = (float*)(smem + OF_B1);
    float* s_b2 = (float*)(smem + OF_B2);
    float* s_e2 = (float*)(smem + OF_E2);
    float* s_cd = (float*)(smem + OF_CD);
    unsigned short* s_ci = (unsigned short*)(smem + OF_CI);

    const int tid = threadIdx.x;
    const int warp = tid >> 5, lane = tid & 31;

    // ---- init: weights, biases, e2; CBH staged into HT ----
    for (int i = tid; i < HID; i += ETHREADS) s_b1[i] = b1[i];
    for (int i = tid; i < LAT; i += ETHREADS) s_b2[i] = b2[i];
    for (int i = tid; i < NCODES * 32; i += ETHREADS) {      // CBH staging
        int c = i >> 5, w = i & 31;
        uint32_t lo;
        uint32_t hi = pack2_split_hi(cb[c * LAT + 2 * w], cb[c * LAT + 2 * w + 1], lo);
        *(uint32_t*)(smem + OF_HT + SWZ_W(c, w)) = hi;
        (void)lo;
    }
    for (int i = tid; i < LAT * 64; i += ETHREADS) {         // W2^T split
        int n = i >> 6, kw = i & 63;
        uint32_t lo;
        uint32_t hi = pack2_split_hi(w2[2 * kw * LAT + n], w2[(2 * kw + 1) * LAT + n], lo);
        int khalf = kw >> 5, w = kw & 31;
        *(uint32_t*)(smem + OF_W2 + khalf * 8192 + SWZ_W(n, w))         = hi;
        *(uint32_t*)(smem + OF_W2 + 16384 + khalf * 8192 + SWZ_W(n, w)) = lo;
    }
    for (int i = tid; i < HID * 14; i += ETHREADS) {         // W1^T split
        int n = i / 14, kw = i - n * 14;
        uint32_t lo;
        uint32_t hi = pack2_split_hi(w1[2 * kw * HID + n], w1[(2 * kw + 1) * HID + n], lo);
        *(uint32_t*)(smem + OF_W1TH + SWZ64_W(n, kw)) = hi;
        *(uint32_t*)(smem + OF_W1TL + SWZ64_W(n, kw)) = lo;
    }
    for (int i = tid; i < HID * 2; i += ETHREADS) {          // W1T k-pad
        int n = i >> 1, w = 14 + (i & 1);
        *(uint32_t*)(smem + OF_W1TH + SWZ64_W(n, w)) = 0;
        *(uint32_t*)(smem + OF_W1TL + SWZ64_W(n, w)) = 0;
    }
    for (int c = tid; c < NCODES; c += ETHREADS) {
        float s = 0.f;
        for (int k = 0; k < LAT; k++) { float v = cb[c * LAT + k]; s = fmaf(v, v, s); }
        s_e2[c] = s;
    }
    __syncthreads();

    // mma lane-role constants
    const int g = lane >> 2, t = lane & 3;
    const int a_roff = (lane & 7) + 8 * ((lane >> 3) & 1);
    const int a_ch   = lane >> 4;
    const int b_row0 = (lane & 7) + 8 * ((lane >> 4) & 1);
    const int b_ch   = (lane >> 3) & 1;

    // ---- codebook HI fragments -> registers ----
    uint32_t bregH[4][4][2];
    #pragma unroll
    for (int pp = 0; pp < 2; pp++)
        #pragma unroll
        for (int kk = 0; kk < 4; kk++) {
            uint32_t r4[4];
            ldsm_x4(r4, smb + OF_HT + SWZ_C(warp * 32 + pp * 16 + b_row0, 2 * kk + b_ch));
            bregH[2 * pp][kk][0] = r4[0];     bregH[2 * pp][kk][1] = r4[1];
            bregH[2 * pp + 1][kk][0] = r4[2]; bregH[2 * pp + 1][kk][1] = r4[3];
        }
    __syncthreads();
    // ---- restage CBL into HT, then codebook LO fragments -> registers ----
    for (int i = tid; i < NCODES * 32; i += ETHREADS) {
        int c = i >> 5, w = i & 31;
        uint32_t lo;
        (void)pack2_split_hi(cb[c * LAT + 2 * w], cb[c * LAT + 2 * w + 1], lo);
        *(uint32_t*)(smem + OF_HT + SWZ_W(c, w)) = lo;
    }
    __syncthreads();
    uint32_t bregL[4][4][2];
    #pragma unroll
    for (int pp = 0; pp < 2; pp++)
        #pragma unroll
        for (int kk = 0; kk < 4; kk++) {
            uint32_t r4[4];
            ldsm_x4(r4, smb + OF_HT + SWZ_C(warp * 32 + pp * 16 + b_row0, 2 * kk + b_ch));
            bregL[2 * pp][kk][0] = r4[0];     bregL[2 * pp][kk][1] = r4[1];
            bregL[2 * pp + 1][kk][0] = r4[2]; bregL[2 * pp + 1][kk][1] = r4[3];
        }
    __syncthreads();   // HT now free for h tiles

    const int rbw = warp >> 1, nhf = warp & 1;
    const int R0w = rbw * 16;
    const int rA = R0w + g, rB = rA + 8;
    float vq_local = 0.f, rec_local = 0.f;

    // ---- prefetch first tile's x fragment into registers ----
    float2 xf[8];
    load_xfrag(x, blockIdx.x, R0w, g, t, xf);

    for (int tle = blockIdx.x; tle < NTILES; tle += GRID1) {
        // -------- P1: split xf -> A-frags; prefetch next xf; enc1 MMA --------
        {
            uint32_t xH[2][4], xL[2][4];
            #pragma unroll
            for (int kk = 0; kk < 2; kk++)
                #pragma unroll
                for (int seg = 0; seg < 2; seg++) {
                    int idx = kk * 4 + seg * 2;
                    xH[kk][seg * 2]     = pack2_split_hi(xf[idx].x, xf[idx].y, xL[kk][seg * 2]);
                    xH[kk][seg * 2 + 1] = pack2_split_hi(xf[idx + 1].x, xf[idx + 1].y, xL[kk][seg * 2 + 1]);
                }
            // issue next tile's loads (hidden behind P1 MMA + P2 + P3)
            if (tle + GRID1 < NTILES)
                load_xfrag(x, tle + GRID1, R0w, g, t, xf);

            #pragma unroll
            for (int half = 0; half < 2; half++) {
                float acc[4][4];
                #pragma unroll
                for (int nb = 0; nb < 4; nb++)
                    #pragma unroll
                    for (int u = 0; u < 4; u++) acc[nb][u] = 0.f;

                #pragma unroll
                for (int kk = 0; kk < 2; kk++) {
                    #pragma unroll
                    for (int p2 = 0; p2 < 2; p2++) {
                        int pp = half * 2 + p2;
                        int nrow = nhf * 64 + pp * 16 + b_row0;
                        uint32_t offB = SWZ64_C(nrow, 2 * kk + b_ch);
                        uint32_t bH[4], bL[4];
                        ldsm_x4(bH, smb + OF_W1TH + offB);
                        ldsm_x4(bL, smb + OF_W1TL + offB);
                        mma16816(acc[2 * p2], xH[kk], bH[0], bH[1]);
                        mma16816(acc[2 * p2], xH[kk], bL[0], bL[1]);
                        mma16816(acc[2 * p2], xL[kk], bH[0], bH[1]);
                        mma16816(acc[2 * p2 + 1], xH[kk], bH[2], bH[3]);
                        mma16816(acc[2 * p2 + 1], xH[kk], bL[2], bL[3]);
                        mma16816(acc[2 * p2 + 1], xL[kk], bH[2], bH[3]);
                    }
                }
                #pragma unroll
                for (int nb = 0; nb < 4; nb++) {
                    int gnb = half * 4 + nb;
                    int c = nhf * 64 + gnb * 8 + 2 * t;
                    float bb0 = s_b1[c], bb1 = s_b1[c + 1];
                    int w = gnb * 4 + t;
                    float h00 = fmaxf(acc[nb][0] + bb0, 0.f);
                    float h01 = fmaxf(acc[nb][1] + bb1, 0.f);
                    float h10 = fmaxf(acc[nb][2] + bb0, 0.f);
                    float h11 = fmaxf(acc[nb][3] + bb1, 0.f);
                    uint32_t lo;
                    uint32_t hi = pack2_split_hi(h00, h01, lo);
                    *(uint32_t*)(smem + OF_HT + nhf * 16384 + SWZ_W(rA, w)) = hi;
                    *(uint32_t*)(smem + OF_HT + 32768 + nhf * 16384 + SWZ_W(rA, w)) = lo;
                    hi = pack2_split_hi(h10, h11, lo);
                    *(uint32_t*)(smem + OF_HT + nhf * 16384 + SWZ_W(rB, w)) = hi;
                    *(uint32_t*)(smem + OF_HT + 32768 + nhf * 16384 + SWZ_W(rB, w)) = lo;
                }
            }
        }
        // pair barrier: h producers == consumers (warps 2*rbw, 2*rbw+1)
        asm volatile("bar.sync %0, 64;" :: "r"(rbw + 1) : "memory");

        // -------- P2: enc2 MMA: z = h @ W2 + b2 -> ZB; fold ||z||^2 into vq --------
        {
            const int a_row2 = R0w + a_roff;
            float acc2[4][4];
            #pragma unroll
            for (int nb = 0; nb < 4; nb++)
                #pragma unroll
                for (int u = 0; u < 4; u++) acc2[nb][u] = 0.f;

            #pragma unroll
            for (int khalf = 0; khalf < 2; khalf++) {
                #pragma unroll
                for (int kk = 0; kk < 4; kk++) {
                    uint32_t aH[4], aL[4];
                    uint32_t offA = SWZ_C(a_row2, 2 * kk + a_ch);
                    ldsm_x4(aH, smb + OF_HT + khalf * 16384 + offA);
                    ldsm_x4(aL, smb + OF_HT + 32768 + khalf * 16384 + offA);
                    #pragma unroll
                    for (int pp = 0; pp < 2; pp++) {
                        int nrow = nhf * 32 + pp * 16 + b_row0;
                        uint32_t offB = SWZ_C(nrow, 2 * kk + b_ch);
                        uint32_t bH[4], bL[4];
                        ldsm_x4(bH, smb + OF_W2 + khalf * 8192 + offB);
                        ldsm_x4(bL, smb + OF_W2 + 16384 + khalf * 8192 + offB);
                        mma16816(acc2[2 * pp], aH, bH[0], bH[1]);
                        mma16816(acc2[2 * pp], aH, bL[0], bL[1]);
                        mma16816(acc2[2 * pp], aL, bH[0], bH[1]);
                        mma16816(acc2[2 * pp + 1], aH, bH[2], bH[3]);
                        mma16816(acc2[2 * pp + 1], aH, bL[2], bL[3]);
                        mma16816(acc2[2 * pp + 1], aL, bH[2], bH[3]);
                    }
                }
            }
            float z2sum = 0.f;
            #pragma unroll
            for (int nb = 0; nb < 4; nb++) {
                int c0 = nhf * 32 + nb * 8 + 2 * t;
                int w = c0 >> 1;
                float bb0 = s_b2[c0], bb1 = s_b2[c0 + 1];
                float z00 = acc2[nb][0] + bb0, z01 = acc2[nb][1] + bb1;
                float z10 = acc2[nb][2] + bb0, z11 = acc2[nb][3] + bb1;
                z2sum = fmaf(z00, z00, fmaf(z01, z01, z2sum));
                z2sum = fmaf(z10, z10, fmaf(z11, z11, z2sum));
                uint32_t lo;
                uint32_t hi = pack2_split_hi(z00, z01, lo);
                *(uint32_t*)(smem + OF_ZBH + SWZ_W(rA, w)) = hi;
                *(uint32_t*)(smem + OF_ZBL + SWZ_W(rA, w)) = lo;
                hi = pack2_split_hi(z10, z11, lo);
                *(uint32_t*)(smem + OF_ZBH + SWZ_W(rB, w)) = hi;
                *(uint32_t*)(smem + OF_ZBL + SWZ_W(rB, w)) = lo;
            }
            vq_local += z2sum;
        }
        __syncthreads();   // C

        // -------- P3: distance MMA, fully register-fed B operands --------
        #pragma unroll 1
        for (int rb = 0; rb < 8; rb++) {
            const int a_row3 = rb * 16 + a_roff;
            uint32_t afH[2][4], afL[2][4];
            {
                uint32_t off = SWZ_C(a_row3, a_ch);
                ldsm_x4(afH[0], smb + OF_ZBH + off);
                ldsm_x4(afL[0], smb + OF_ZBL + off);
            }
            float acc3[4][4];
            #pragma unroll
            for (int nb = 0; nb < 4; nb++)
                #pragma unroll
                for (int u = 0; u < 4; u++) acc3[nb][u] = 0.f;

            #pragma unroll
            for (int kk = 0; kk < 4; kk++) {
                int cur = kk & 1;
                if (kk < 3) {
                    uint32_t off = SWZ_C(a_row3, 2 * (kk + 1) + a_ch);
                    ldsm_x4(afH[cur ^ 1], smb + OF_ZBH + off);
                    ldsm_x4(afL[cur ^ 1], smb + OF_ZBL + off);
                }
                #pragma unroll
                for (int nb = 0; nb < 4; nb++) {
                    mma16816(acc3[nb], afH[cur], bregH[nb][kk][0], bregH[nb][kk][1]);  // zH*eH
                    mma16816(acc3[nb], afL[cur], bregH[nb][kk][0], bregH[nb][kk][1]);  // zL*eH
                    mma16816(acc3[nb], afH[cur], bregL[nb][kk][0], bregL[nb][kk][1]);  // zH*eL
                }
            }
            float mA = 3.4e38f, mB = 3.4e38f; int iA = 0, iB = 0;
            #pragma unroll
            for (int nb = 0; nb < 4; nb++) {
                int c0 = warp * 32 + nb * 8 + 2 * t;
                float e0 = s_e2[c0], e1 = s_e2[c0 + 1];
                float d00 = fmaf(-2.f, acc3[nb][0], e0);
                float d01 = fmaf(-2.f, acc3[nb][1], e1);
                float d10 = fmaf(-2.f, acc3[nb][2], e0);
                float d11 = fmaf(-2.f, acc3[nb][3], e1);
                if (d00 < mA) { mA = d00; iA = c0; }
                if (d01 < mA) { mA = d01; iA = c0 + 1; }
                if (d10 < mB) { mB = d10; iB = c0; }
                if (d11 < mB) { mB = d11; iB = c0 + 1; }
            }
            #pragma unroll
            for (int off = 1; off <= 2; off <<= 1) {
                float ov = __shfl_xor_sync(0xffffffffu, mA, off);
                int   oi = __shfl_xor_sync(0xffffffffu, iA, off);
                if (ov < mA || (ov == mA && oi < iA)) { mA = ov; iA = oi; }
                ov = __shfl_xor_sync(0xffffffffu, mB, off);
                oi = __shfl_xor_sync(0xffffffffu, iB, off);
                if (ov < mB || (ov == mB && oi < iB)) { mB = ov; iB = oi; }
            }
            if (t == 0) {
                s_cd[(rb * 16 + g) * 17 + warp]     = mA;
                s_ci[(rb * 16 + g) * 17 + warp]     = (unsigned short)iA;
                s_cd[(rb * 16 + 8 + g) * 17 + warp] = mB;
                s_ci[(rb * 16 + 8 + g) * 17 + warp] = (unsigned short)iB;
            }
        }
        __syncthreads();   // D

        // -------- P4: scan candidates; fused recon gather + out + rec loss --------
        if (tid < TILE_M) {
            const float* rowd = s_cd + tid * 17;
            const unsigned short* rowi = s_ci + tid * 17;
            float best = rowd[0];
            int   bi   = rowi[0];
            #pragma unroll
            for (int w = 1; w < EWARPS; w++) {
                float dw = rowd[w];
                if (dw < best) { best = dw; bi = rowi[w]; }
            }
            vq_local += best;

            // recon = g_tbl[bi]; write out; accumulate recon loss
            const float4* trow = (const float4*)(g_tbl + bi * IN_DIM);
            const float4* xrow = (const float4*)(x + ((size_t)tle * TILE_M + tid) * IN_DIM);
            float4* orow = (float4*)(out + ((size_t)tle * TILE_M + tid) * IN_DIM);
            #pragma unroll
            for (int w = 0; w < 7; w++) {
                float4 tv = trow[w];
                float4 xv = xrow[w];
                orow[w] = tv;
                float d0 = tv.x - xv.x, d1 = tv.y - xv.y;
                float d2 = tv.z - xv.z, d3 = tv.w - xv.w;
                rec_local = fmaf(d0, d0, fmaf(d1, d1, fmaf(d2, d2, fmaf(d3, d3, rec_local))));
            }
        }
        // no barrier: next P1 writes HT (pair-local, last read pre-C);
        // next P2 writes ZB (last read pre-D); CD/CI next written post-C.
    }

    // ---- reduce vq + rec ----
    #pragma unroll
    for (int off = 16; off; off >>= 1) {
        vq_local  += __shfl_down_sync(0xffffffffu, vq_local, off);
        rec_local += __shfl_down_sync(0xffffffffu, rec_local, off);
    }
    __syncthreads();
    float* s_red = (float*)(smem + OF_CD);
    if (lane == 0) { s_red[warp] = vq_local; s_red[EWARPS + warp] = rec_local; }
    __syncthreads();
    if (tid == 0) {
        float sv = 0.f, sr = 0.f;
        for (int w = 0; w < EWARPS; w++) { sv += s_red[w]; sr += s_red[EWARPS + w]; }
        g_vq_part[blockIdx.x]  = sv;
        g_rec_part[blockIdx.x] = sr;
    }
}

// ============================================================================
// decoder table for 512 codes (exact fp32)
// ============================================================================
__global__ void k_hd(const float* __restrict__ cb,
                     const float* __restrict__ dw1, const float* __restrict__ db1)
{
    int gid = blockIdx.x * blockDim.x + threadIdx.x;
    int c = gid >> 7, j = gid & 127;
    float acc = db1[j];
    const float* q = cb + c * LAT;
    #pragma unroll 8
    for (int k = 0; k < LAT; k++) acc = fmaf(q[k], dw1[k * HID + j], acc);
    g_hd[gid] = fmaxf(acc, 0.f);
}

__global__ void k_tbl(const float* __restrict__ dw2, const float* __restrict__ db2)
{
    int gid = blockIdx.x * blockDim.x + threadIdx.x;
    int c = gid / IN_DIM, j = gid - c * IN_DIM;
    float acc = db2[j];
    const float* hd = g_hd + c * HID;
    #pragma unroll 8
    for (int k = 0; k < HID; k++) acc = fmaf(hd[k], dw2[k * IN_DIM + j], acc);
    g_tbl[gid] = acc;
}

// ============================================================================
// finalize scalar losses — parallel double reduction (deterministic)
// ============================================================================
#define FIN_THREADS 256
__global__ void k_final(float* __restrict__ out)
{
    __shared__ double s_v[FIN_THREADS], s_r[FIN_THREADS];
    int tid = threadIdx.x;
    double v = 0.0, r = 0.0;
    if (tid < GRID1) {
        v = (double)g_vq_part[tid];
        r = (double)g_rec_part[tid];
    }
    s_v[tid] = v; s_r[tid] = r;
    __syncthreads();
    #pragma unroll
    for (int off = FIN_THREADS / 2; off > 0; off >>= 1) {
        if (tid < off) {
            s_v[tid] += s_v[tid + off];
            s_r[tid] += s_r[tid + off];
        }
        __syncthreads();
    }
    if (tid == 0) {
        out[(long)B_TOTAL * IN_DIM]     = (float)(s_r[0] / ((double)B_TOTAL * IN_DIM));
        out[(long)B_TOTAL * IN_DIM + 1] = (float)(1.25 * s_v[0] / ((double)B_TOTAL * LAT));
    }
}

// ============================================================================
extern "C" void kernel_launch(void* const* d_in, const int* in_sizes, int n_in,
                              void* d_out, int out_size)
{
    const float* x    = (const float*)d_in[0];
    const float* ew1  = (const float*)d_in[1];
    const float* eb1  = (const float*)d_in[2];
    const float* ew2  = (const float*)d_in[3];
    const float* eb2  = (const float*)d_in[4];
    const float* cb   = (const float*)d_in[5];
    const float* dw1  = (const float*)d_in[6];
    const float* db1  = (const float*)d_in[7];
    const float* dw2  = (const float*)d_in[8];
    const float* db2  = (const float*)d_in[9];
    float* out = (float*)d_out;

    cudaFuncSetAttribute(k_encode, cudaFuncAttributeMaxDynamicSharedMemorySize, SMEM_E);

    k_hd<<<(NCODES * HID) / 256, 256>>>(cb, dw1, db1);
    k_tbl<<<(NCODES * IN_DIM) / 256, 256>>>(dw2, db2);
    k_encode<<<GRID1, ETHREADS, SMEM_E>>>(x, ew1, eb1, ew2, eb2, cb, out);
    k_final<<<FIN_THREADS / 256, FIN_THREADS>>>(out);
}

// round 17
// speedup vs baseline: 1.2247x; 1.0013x over previous
#include <cuda_runtime.h>
#include <cuda_bf16.h>
#include <cstdint>

#define B_TOTAL 262144
#define IN_DIM 28
#define HID 128
#define LAT 64
#define NCODES 512
#define GRID1 148
#define TILE_M 128
#define NTILES (B_TOTAL / TILE_M)   // 2048

#define ETHREADS 512
#define EWARPS 16

// ---- k_encode smem layout (bytes) ----
#define OF_HT    0                      // 65536: h tiles HH0,HH1,HL0,HL1; CB staging at init
#define OF_ZBH   65536                  // z hi 128x128B = 16384
#define OF_ZBL   81920                  // z lo 16384
#define OF_W2    98304                  // W2H0,W2H1,W2L0,W2L1 (8K each) = 32768
#define OF_W1TH  131072                 // W1^T hi [128n][32k] 64B rows = 8192
#define OF_W1TL  139264                 // 8192
#define OF_B1    147456                 // 512
#define OF_B2    147968                 // 256
#define OF_E2    148224                 // 2048
#define OF_CD    150272                 // float[128][17] = 8704 (8B aligned; reused for reductions)
#define OF_CI    158976                 // u16[128][17]   = 4352
#define SMEM_E   163328

// XOR swizzle, 128B rows (16B granularity)
#define SWZ_W(row, w)  ((row) * 128 + ((((w) >> 2) ^ ((row) & 7)) << 4) + ((w) & 3) * 4)
#define SWZ_C(row, ch) ((row) * 128 + ((((ch)) ^ ((row) & 7)) << 4))
// XOR swizzle, 64B rows
#define SWZ64_W(row, w)  ((row) * 64 + ((((w) >> 2) ^ (((row) >> 1) & 3)) << 4) + ((w) & 3) * 4)
#define SWZ64_C(row, ch) ((row) * 64 + ((((ch)) ^ (((row) >> 1) & 3)) << 4))

__device__ float        g_vq_part[GRID1];
__device__ float        g_rec_part[GRID1];
__device__ float        g_tbl[NCODES * IN_DIM];
__device__ unsigned int g_ticket;   // zero-init; reset by finalizing block each launch

// ---------------- helpers ----------------
__device__ __forceinline__ uint32_t smem_u32_of(const void* p) {
    uint32_t a;
    asm("{ .reg .u64 t; cvta.to.shared.u64 t, %1; cvt.u32.u64 %0, t; }" : "=r"(a) : "l"(p));
    return a;
}
__device__ __forceinline__ void ldsm_x4(uint32_t* r, uint32_t addr) {
    asm volatile("ldmatrix.sync.aligned.m8n8.x4.shared.b16 {%0,%1,%2,%3}, [%4];"
        : "=r"(r[0]), "=r"(r[1]), "=r"(r[2]), "=r"(r[3]) : "r"(addr));
}
__device__ __forceinline__ void mma16816(float* d, const uint32_t* a, uint32_t b0, uint32_t b1) {
    asm volatile("mma.sync.aligned.m16n8k16.row.col.f32.bf16.bf16.f32 "
        "{%0,%1,%2,%3}, {%4,%5,%6,%7}, {%8,%9}, {%0,%1,%2,%3};"
        : "+f"(d[0]), "+f"(d[1]), "+f"(d[2]), "+f"(d[3])
        : "r"(a[0]), "r"(a[1]), "r"(a[2]), "r"(a[3]), "r"(b0), "r"(b1));
}
// split two floats into packed-bf16 hi + packed-bf16 lo (residual), rn rounding.
// PTX cvt d,a,b puts a in HIGH half, b in LOW half -> pass (b_val, a_val).
__device__ __forceinline__ uint32_t pack2_split_hi(float a, float b, uint32_t& lo_out) {
    uint32_t hi;
    asm("cvt.rn.bf16x2.f32 %0, %1, %2;" : "=r"(hi) : "f"(b), "f"(a));
    float ha = __uint_as_float(hi << 16);
    float hb = __uint_as_float(hi & 0xffff0000u);
    float la = a - ha, lb = b - hb;
    asm("cvt.rn.bf16x2.f32 %0, %1, %2;" : "=r"(lo_out) : "f"(lb), "f"(la));
    return hi;
}

// load this warp's x fragment raw values for one tile (8 float2 per lane)
__device__ __forceinline__ void load_xfrag(const float* __restrict__ x,
                                           int tle, int R0w, int g, int t,
                                           float2 xf[8])
{
    const float* xa = x + ((size_t)tle * TILE_M + R0w + g) * IN_DIM;
    const float* xb = xa + 8 * IN_DIM;
    #pragma unroll
    for (int kk = 0; kk < 2; kk++)
        #pragma unroll
        for (int seg = 0; seg < 2; seg++) {
            int k = kk * 16 + seg * 8 + 2 * t;
            int idx = kk * 4 + seg * 2;
            if (k < IN_DIM) {
                xf[idx]     = *(const float2*)(xa + k);
                xf[idx + 1] = *(const float2*)(xb + k);
            } else {
                xf[idx]     = make_float2(0.f, 0.f);
                xf[idx + 1] = make_float2(0.f, 0.f);
            }
        }
}

// ============================================================================
// k_table: decoder table for 512 codes (exact fp32), hd kept in SMEM.
// One block per code: 128 threads build hd[128], then 28 compute the row.
// ============================================================================
__global__ void __launch_bounds__(128)
k_table(const float* __restrict__ cb,
        const float* __restrict__ dw1, const float* __restrict__ db1,
        const float* __restrict__ dw2, const float* __restrict__ db2)
{
    __shared__ float s_hd[HID];
    const int c = blockIdx.x, j = threadIdx.x;
    float acc = db1[j];
    const float* q = cb + c * LAT;
    #pragma unroll 8
    for (int k = 0; k < LAT; k++) acc = fmaf(q[k], dw1[k * HID + j], acc);
    s_hd[j] = fmaxf(acc, 0.f);
    __syncthreads();
    if (j < IN_DIM) {
        float a2 = db2[j];
        #pragma unroll 8
        for (int k = 0; k < HID; k++) a2 = fmaf(s_hd[k], dw2[k * IN_DIM + j], a2);
        g_tbl[c * IN_DIM + j] = a2;
    }
}

// ============================================================================
// K1: encoder + fused recon + last-block loss finalize
// ============================================================================
__global__ void __launch_bounds__(ETHREADS, 1)
k_encode(const float* __restrict__ x,
         const float* __restrict__ w1, const float* __restrict__ b1,
         const float* __restrict__ w2, const float* __restrict__ b2,
         const float* __restrict__ cb, float* __restrict__ out)
{
    extern __shared__ char smem[];
    const uint32_t smb = smem_u32_of(smem);

    float* s_b1 = (float*)(smem + OF_B1);
    float* s_b2 = (float*)(smem + OF_B2);
    float* s_e2 = (float*)(smem + OF_E2);
    float* s_cd = (float*)(smem + OF_CD);
    unsigned short* s_ci = (unsigned short*)(smem + OF_CI);

    const int tid = threadIdx.x;
    const int warp = tid >> 5, lane = tid & 31;

    // ---- init: weights, biases, e2; CBH staged into HT ----
    for (int i = tid; i < HID; i += ETHREADS) s_b1[i] = b1[i];
    for (int i = tid; i < LAT; i += ETHREADS) s_b2[i] = b2[i];
    for (int i = tid; i < NCODES * 32; i += ETHREADS) {      // CBH staging
        int c = i >> 5, w = i & 31;
        uint32_t lo;
        uint32_t hi = pack2_split_hi(cb[c * LAT + 2 * w], cb[c * LAT + 2 * w + 1], lo);
        *(uint32_t*)(smem + OF_HT + SWZ_W(c, w)) = hi;
        (void)lo;
    }
    for (int i = tid; i < LAT * 64; i += ETHREADS) {         // W2^T split
        int n = i >> 6, kw = i & 63;
        uint32_t lo;
        uint32_t hi = pack2_split_hi(w2[2 * kw * LAT + n], w2[(2 * kw + 1) * LAT + n], lo);
        int khalf = kw >> 5, w = kw & 31;
        *(uint32_t*)(smem + OF_W2 + khalf * 8192 + SWZ_W(n, w))         = hi;
        *(uint32_t*)(smem + OF_W2 + 16384 + khalf * 8192 + SWZ_W(n, w)) = lo;
    }
    for (int i = tid; i < HID * 14; i += ETHREADS) {         // W1^T split
        int n = i / 14, kw = i - n * 14;
        uint32_t lo;
        uint32_t hi = pack2_split_hi(w1[2 * kw * HID + n], w1[(2 * kw + 1) * HID + n], lo);
        *(uint32_t*)(smem + OF_W1TH + SWZ64_W(n, kw)) = hi;
        *(uint32_t*)(smem + OF_W1TL + SWZ64_W(n, kw)) = lo;
    }
    for (int i = tid; i < HID * 2; i += ETHREADS) {          // W1T k-pad
        int n = i >> 1, w = 14 + (i & 1);
        *(uint32_t*)(smem + OF_W1TH + SWZ64_W(n, w)) = 0;
        *(uint32_t*)(smem + OF_W1TL + SWZ64_W(n, w)) = 0;
    }
    for (int c = tid; c < NCODES; c += ETHREADS) {
        float s = 0.f;
        for (int k = 0; k < LAT; k++) { float v = cb[c * LAT + k]; s = fmaf(v, v, s); }
        s_e2[c] = s;
    }
    __syncthreads();

    // mma lane-role constants
    const int g = lane >> 2, t = lane & 3;
    const int a_roff = (lane & 7) + 8 * ((lane >> 3) & 1);
    const int a_ch   = lane >> 4;
    const int b_row0 = (lane & 7) + 8 * ((lane >> 4) & 1);
    const int b_ch   = (lane >> 3) & 1;

    // ---- codebook HI fragments -> registers ----
    uint32_t bregH[4][4][2];
    #pragma unroll
    for (int pp = 0; pp < 2; pp++)
        #pragma unroll
        for (int kk = 0; kk < 4; kk++) {
            uint32_t r4[4];
            ldsm_x4(r4, smb + OF_HT + SWZ_C(warp * 32 + pp * 16 + b_row0, 2 * kk + b_ch));
            bregH[2 * pp][kk][0] = r4[0];     bregH[2 * pp][kk][1] = r4[1];
            bregH[2 * pp + 1][kk][0] = r4[2]; bregH[2 * pp + 1][kk][1] = r4[3];
        }
    __syncthreads();
    // ---- restage CBL into HT, then codebook LO fragments -> registers ----
    for (int i = tid; i < NCODES * 32; i += ETHREADS) {
        int c = i >> 5, w = i & 31;
        uint32_t lo;
        (void)pack2_split_hi(cb[c * LAT + 2 * w], cb[c * LAT + 2 * w + 1], lo);
        *(uint32_t*)(smem + OF_HT + SWZ_W(c, w)) = lo;
    }
    __syncthreads();
    uint32_t bregL[4][4][2];
    #pragma unroll
    for (int pp = 0; pp < 2; pp++)
        #pragma unroll
        for (int kk = 0; kk < 4; kk++) {
            uint32_t r4[4];
            ldsm_x4(r4, smb + OF_HT + SWZ_C(warp * 32 + pp * 16 + b_row0, 2 * kk + b_ch));
            bregL[2 * pp][kk][0] = r4[0];     bregL[2 * pp][kk][1] = r4[1];
            bregL[2 * pp + 1][kk][0] = r4[2]; bregL[2 * pp + 1][kk][1] = r4[3];
        }
    __syncthreads();   // HT now free for h tiles

    const int rbw = warp >> 1, nhf = warp & 1;
    const int R0w = rbw * 16;
    const int rA = R0w + g, rB = rA + 8;
    float vq_local = 0.f, rec_local = 0.f;

    // ---- prefetch first tile's x fragment into registers ----
    float2 xf[8];
    load_xfrag(x, blockIdx.x, R0w, g, t, xf);

    for (int tle = blockIdx.x; tle < NTILES; tle += GRID1) {
        // -------- P1: split xf -> A-frags; prefetch next xf; enc1 MMA --------
        {
            uint32_t xH[2][4], xL[2][4];
            #pragma unroll
            for (int kk = 0; kk < 2; kk++)
                #pragma unroll
                for (int seg = 0; seg < 2; seg++) {
                    int idx = kk * 4 + seg * 2;
                    xH[kk][seg * 2]     = pack2_split_hi(xf[idx].x, xf[idx].y, xL[kk][seg * 2]);
                    xH[kk][seg * 2 + 1] = pack2_split_hi(xf[idx + 1].x, xf[idx + 1].y, xL[kk][seg * 2 + 1]);
                }
            // issue next tile's loads (hidden behind P1 MMA + P2 + P3)
            if (tle + GRID1 < NTILES)
                load_xfrag(x, tle + GRID1, R0w, g, t, xf);

            #pragma unroll
            for (int half = 0; half < 2; half++) {
                float acc[4][4];
                #pragma unroll
                for (int nb = 0; nb < 4; nb++)
                    #pragma unroll
                    for (int u = 0; u < 4; u++) acc[nb][u] = 0.f;

                #pragma unroll
                for (int kk = 0; kk < 2; kk++) {
                    #pragma unroll
                    for (int p2 = 0; p2 < 2; p2++) {
                        int pp = half * 2 + p2;
                        int nrow = nhf * 64 + pp * 16 + b_row0;
                        uint32_t offB = SWZ64_C(nrow, 2 * kk + b_ch);
                        uint32_t bH[4], bL[4];
                        ldsm_x4(bH, smb + OF_W1TH + offB);
                        ldsm_x4(bL, smb + OF_W1TL + offB);
                        mma16816(acc[2 * p2], xH[kk], bH[0], bH[1]);
                        mma16816(acc[2 * p2], xH[kk], bL[0], bL[1]);
                        mma16816(acc[2 * p2], xL[kk], bH[0], bH[1]);
                        mma16816(acc[2 * p2 + 1], xH[kk], bH[2], bH[3]);
                        mma16816(acc[2 * p2 + 1], xH[kk], bL[2], bL[3]);
                        mma16816(acc[2 * p2 + 1], xL[kk], bH[2], bH[3]);
                    }
                }
                #pragma unroll
                for (int nb = 0; nb < 4; nb++) {
                    int gnb = half * 4 + nb;
                    int c = nhf * 64 + gnb * 8 + 2 * t;
                    float bb0 = s_b1[c], bb1 = s_b1[c + 1];
                    int w = gnb * 4 + t;
                    float h00 = fmaxf(acc[nb][0] + bb0, 0.f);
                    float h01 = fmaxf(acc[nb][1] + bb1, 0.f);
                    float h10 = fmaxf(acc[nb][2] + bb0, 0.f);
                    float h11 = fmaxf(acc[nb][3] + bb1, 0.f);
                    uint32_t lo;
                    uint32_t hi = pack2_split_hi(h00, h01, lo);
                    *(uint32_t*)(smem + OF_HT + nhf * 16384 + SWZ_W(rA, w)) = hi;
                    *(uint32_t*)(smem + OF_HT + 32768 + nhf * 16384 + SWZ_W(rA, w)) = lo;
                    hi = pack2_split_hi(h10, h11, lo);
                    *(uint32_t*)(smem + OF_HT + nhf * 16384 + SWZ_W(rB, w)) = hi;
                    *(uint32_t*)(smem + OF_HT + 32768 + nhf * 16384 + SWZ_W(rB, w)) = lo;
                }
            }
        }
        // pair barrier: h producers == consumers (warps 2*rbw, 2*rbw+1)
        asm volatile("bar.sync %0, 64;" :: "r"(rbw + 1) : "memory");

        // -------- P2: enc2 MMA: z = h @ W2 + b2 -> ZB; fold ||z||^2 into vq --------
        {
            const int a_row2 = R0w + a_roff;
            float acc2[4][4];
            #pragma unroll
            for (int nb = 0; nb < 4; nb++)
                #pragma unroll
                for (int u = 0; u < 4; u++) acc2[nb][u] = 0.f;

            #pragma unroll
            for (int khalf = 0; khalf < 2; khalf++) {
                #pragma unroll
                for (int kk = 0; kk < 4; kk++) {
                    uint32_t aH[4], aL[4];
                    uint32_t offA = SWZ_C(a_row2, 2 * kk + a_ch);
                    ldsm_x4(aH, smb + OF_HT + khalf * 16384 + offA);
                    ldsm_x4(aL, smb + OF_HT + 32768 + khalf * 16384 + offA);
                    #pragma unroll
                    for (int pp = 0; pp < 2; pp++) {
                        int nrow = nhf * 32 + pp * 16 + b_row0;
                        uint32_t offB = SWZ_C(nrow, 2 * kk + b_ch);
                        uint32_t bH[4], bL[4];
                        ldsm_x4(bH, smb + OF_W2 + khalf * 8192 + offB);
                        ldsm_x4(bL, smb + OF_W2 + 16384 + khalf * 8192 + offB);
                        mma16816(acc2[2 * pp], aH, bH[0], bH[1]);
                        mma16816(acc2[2 * pp], aH, bL[0], bL[1]);
                        mma16816(acc2[2 * pp], aL, bH[0], bH[1]);
                        mma16816(acc2[2 * pp + 1], aH, bH[2], bH[3]);
                        mma16816(acc2[2 * pp + 1], aH, bL[2], bL[3]);
                        mma16816(acc2[2 * pp + 1], aL, bH[2], bH[3]);
                    }
                }
            }
            float z2sum = 0.f;
            #pragma unroll
            for (int nb = 0; nb < 4; nb++) {
                int c0 = nhf * 32 + nb * 8 + 2 * t;
                int w = c0 >> 1;
                float bb0 = s_b2[c0], bb1 = s_b2[c0 + 1];
                float z00 = acc2[nb][0] + bb0, z01 = acc2[nb][1] + bb1;
                float z10 = acc2[nb][2] + bb0, z11 = acc2[nb][3] + bb1;
                z2sum = fmaf(z00, z00, fmaf(z01, z01, z2sum));
                z2sum = fmaf(z10, z10, fmaf(z11, z11, z2sum));
                uint32_t lo;
                uint32_t hi = pack2_split_hi(z00, z01, lo);
                *(uint32_t*)(smem + OF_ZBH + SWZ_W(rA, w)) = hi;
                *(uint32_t*)(smem + OF_ZBL + SWZ_W(rA, w)) = lo;
                hi = pack2_split_hi(z10, z11, lo);
                *(uint32_t*)(smem + OF_ZBH + SWZ_W(rB, w)) = hi;
                *(uint32_t*)(smem + OF_ZBL + SWZ_W(rB, w)) = lo;
            }
            vq_local += z2sum;
        }
        __syncthreads();   // C

        // -------- P3: distance MMA, fully register-fed B operands --------
        #pragma unroll 1
        for (int rb = 0; rb < 8; rb++) {
            const int a_row3 = rb * 16 + a_roff;
            uint32_t afH[2][4], afL[2][4];
            {
                uint32_t off = SWZ_C(a_row3, a_ch);
                ldsm_x4(afH[0], smb + OF_ZBH + off);
                ldsm_x4(afL[0], smb + OF_ZBL + off);
            }
            float acc3[4][4];
            #pragma unroll
            for (int nb = 0; nb < 4; nb++)
                #pragma unroll
                for (int u = 0; u < 4; u++) acc3[nb][u] = 0.f;

            #pragma unroll
            for (int kk = 0; kk < 4; kk++) {
                int cur = kk & 1;
                if (kk < 3) {
                    uint32_t off = SWZ_C(a_row3, 2 * (kk + 1) + a_ch);
                    ldsm_x4(afH[cur ^ 1], smb + OF_ZBH + off);
                    ldsm_x4(afL[cur ^ 1], smb + OF_ZBL + off);
                }
                #pragma unroll
                for (int nb = 0; nb < 4; nb++) {
                    mma16816(acc3[nb], afH[cur], bregH[nb][kk][0], bregH[nb][kk][1]);  // zH*eH
                    mma16816(acc3[nb], afL[cur], bregH[nb][kk][0], bregH[nb][kk][1]);  // zL*eH
                    mma16816(acc3[nb], afH[cur], bregL[nb][kk][0], bregL[nb][kk][1]);  // zH*eL
                }
            }
            float mA = 3.4e38f, mB = 3.4e38f; int iA = 0, iB = 0;
            #pragma unroll
            for (int nb = 0; nb < 4; nb++) {
                int c0 = warp * 32 + nb * 8 + 2 * t;
                float e0 = s_e2[c0], e1 = s_e2[c0 + 1];
                float d00 = fmaf(-2.f, acc3[nb][0], e0);
                float d01 = fmaf(-2.f, acc3[nb][1], e1);
                float d10 = fmaf(-2.f, acc3[nb][2], e0);
                float d11 = fmaf(-2.f, acc3[nb][3], e1);
                if (d00 < mA) { mA = d00; iA = c0; }
                if (d01 < mA) { mA = d01; iA = c0 + 1; }
                if (d10 < mB) { mB = d10; iB = c0; }
                if (d11 < mB) { mB = d11; iB = c0 + 1; }
            }
            #pragma unroll
            for (int off = 1; off <= 2; off <<= 1) {
                float ov = __shfl_xor_sync(0xffffffffu, mA, off);
                int   oi = __shfl_xor_sync(0xffffffffu, iA, off);
                if (ov < mA || (ov == mA && oi < iA)) { mA = ov; iA = oi; }
                ov = __shfl_xor_sync(0xffffffffu, mB, off);
                oi = __shfl_xor_sync(0xffffffffu, iB, off);
                if (ov < mB || (ov == mB && oi < iB)) { mB = ov; iB = oi; }
            }
            if (t == 0) {
                s_cd[(rb * 16 + g) * 17 + warp]     = mA;
                s_ci[(rb * 16 + g) * 17 + warp]     = (unsigned short)iA;
                s_cd[(rb * 16 + 8 + g) * 17 + warp] = mB;
                s_ci[(rb * 16 + 8 + g) * 17 + warp] = (unsigned short)iB;
            }
        }
        __syncthreads();   // D

        // -------- P4: scan candidates; fused recon gather + out + rec loss --------
        if (tid < TILE_M) {
            const float* rowd = s_cd + tid * 17;
            const unsigned short* rowi = s_ci + tid * 17;
            float best = rowd[0];
            int   bi   = rowi[0];
            #pragma unroll
            for (int w = 1; w < EWARPS; w++) {
                float dw = rowd[w];
                if (dw < best) { best = dw; bi = rowi[w]; }
            }
            vq_local += best;

            // recon = g_tbl[bi]; write out; accumulate recon loss
            const float4* trow = (const float4*)(g_tbl + bi * IN_DIM);
            const float4* xrow = (const float4*)(x + ((size_t)tle * TILE_M + tid) * IN_DIM);
            float4* orow = (float4*)(out + ((size_t)tle * TILE_M + tid) * IN_DIM);
            #pragma unroll
            for (int w = 0; w < 7; w++) {
                float4 tv = trow[w];
                float4 xv = xrow[w];
                orow[w] = tv;
                float d0 = tv.x - xv.x, d1 = tv.y - xv.y;
                float d2 = tv.z - xv.z, d3 = tv.w - xv.w;
                rec_local = fmaf(d0, d0, fmaf(d1, d1, fmaf(d2, d2, fmaf(d3, d3, rec_local))));
            }
        }
        // no barrier: next P1 writes HT (pair-local, last read pre-C);
        // next P2 writes ZB (last read pre-D); CD/CI next written post-C.
    }

    // ---- reduce vq + rec within block ----
    #pragma unroll
    for (int off = 16; off; off >>= 1) {
        vq_local  += __shfl_down_sync(0xffffffffu, vq_local, off);
        rec_local += __shfl_down_sync(0xffffffffu, rec_local, off);
    }
    __syncthreads();
    float* s_red = (float*)(smem + OF_CD);
    if (lane == 0) { s_red[warp] = vq_local; s_red[EWARPS + warp] = rec_local; }
    __syncthreads();

    __shared__ int s_is_last;
    if (tid == 0) {
        float sv = 0.f, sr = 0.f;
        for (int w = 0; w < EWARPS; w++) { sv += s_red[w]; sr += s_red[EWARPS + w]; }
        g_vq_part[blockIdx.x]  = sv;
        g_rec_part[blockIdx.x] = sr;
        __threadfence();
        unsigned int tk = atomicAdd(&g_ticket, 1u);
        s_is_last = (tk == GRID1 - 1);
    }
    __syncthreads();

    // ---- last block: deterministic double-tree finalize ----
    if (s_is_last) {
        double* d_v = (double*)(smem + OF_CD);        // 256 doubles = 2048 B
        double* d_r = d_v + 256;                      // next 2048 B (fits in CD region)
        if (tid < 256) {
            d_v[tid] = (tid < GRID1) ? (double)g_vq_part[tid]  : 0.0;
            d_r[tid] = (tid < GRID1) ? (double)g_rec_part[tid] : 0.0;
        }
        __syncthreads();
        #pragma unroll
        for (int off = 128; off > 0; off >>= 1) {
            if (tid < off) {
                d_v[tid] += d_v[tid + off];
                d_r[tid] += d_r[tid + off];
            }
            __syncthreads();
        }
        if (tid == 0) {
            out[(long)B_TOTAL * IN_DIM]     = (float)(d_r[0] / ((double)B_TOTAL * IN_DIM));
            out[(long)B_TOTAL * IN_DIM + 1] = (float)(1.25 * d_v[0] / ((double)B_TOTAL * LAT));
            g_ticket = 0;   // reset for next (graph-replayed) launch
        }
    }
}

// ============================================================================
extern "C" void kernel_launch(void* const* d_in, const int* in_sizes, int n_in,
                              void* d_out, int out_size)
{
    const float* x    = (const float*)d_in[0];
    const float* ew1  = (const float*)d_in[1];
    const float* eb1  = (const float*)d_in[2];
    const float* ew2  = (const float*)d_in[3];
    const float* eb2  = (const float*)d_in[4];
    const float* cb   = (const float*)d_in[5];
    const float* dw1  = (const float*)d_in[6];
    const float* db1  = (const float*)d_in[7];
    const float* dw2  = (const float*)d_in[8];
    const float* db2  = (const float*)d_in[9];
    float* out = (float*)d_out;

    cudaFuncSetAttribute(k_encode, cudaFuncAttributeMaxDynamicSharedMemorySize, SMEM_E);

    k_table<<<NCODES, 128>>>(cb, dw1, db1, dw2, db2);
    k_encode<<<GRID1, ETHREADS, SMEM_E>>>(x, ew1, eb1, ew2, eb2, cb, out);
}